// round 11
// baseline (speedup 1.0000x reference)
#include <cuda_runtime.h>

#define N_TOK 8192
#define DDIM  256
#define HDIM  64
#define NEXP  32
#define TM    32        // tokens per ffn tile
#define FFN_CTAS 288    // >= max tiles: 8192/32=256 full + <=31 partial tails

typedef unsigned long long u64;

// packed-f32x2 helpers (sm_100+; ptxas never emits FFMA2 from C++)
#define DUP2(d, s)    asm("mov.b64 %0, {%1, %1};" : "=l"(d) : "f"(s))
#define FMA2(c, a, b) asm("fma.rn.f32x2 %0, %1, %2, %0;" : "+l"(c) : "l"(a), "l"(b))
#define UNPK(lo, hi, p) asm("mov.b64 {%0, %1}, %2;" : "=f"(lo), "=f"(hi) : "l"(p))

// ---------------- scratch (no allocations allowed) ----------------
__device__ int g_idx[N_TOK];
__device__ int g_counts[NEXP];     // zero at init; k_scan resets each call
__device__ int g_off[NEXP + 1];
__device__ int g_cursor[NEXP];
__device__ int g_perm[N_TOK];

// ---------------- kernel 1: router GEMM + fused argmax ----------------
// 256 CTAs x 128 thr; CTA tile 32 tok x 32 exp, K pipelined, f32x2 inner loop.
__global__ void __launch_bounds__(128) k_router(const float* __restrict__ x,
                                                const float* __restrict__ rw,
                                                const float* __restrict__ rb) {
    const int tid = threadIdx.x;
    const int tx  = tid & 7;       // expert group: experts tx*4..tx*4+3
    const int ty  = tid >> 3;      // token group: tokens ty*2, ty*2+1
    const int tok0 = blockIdx.x * 32;

    __shared__ float Xs[32][36];
    __shared__ float Ws[32][32];
    __shared__ int   hist[NEXP];

    if (tid < NEXP) hist[tid] = 0;

    const float4* Xg = (const float4*)x;
    const float4* Wg = (const float4*)rw;

    float4 xv[2], wv[2];
#pragma unroll
    for (int i = 0; i < 2; i++) {
        int lin = tid + i * 128;
        xv[i] = Xg[(size_t)(tok0 + (lin & 31)) * 64 + (lin >> 5)];
        wv[i] = Wg[(size_t)(lin & 31) * 64 + (lin >> 5)];
    }

    u64 acc2[4];
#pragma unroll
    for (int j = 0; j < 4; j++) acc2[j] = 0ull;

    for (int c = 0; c < 8; c++) {
#pragma unroll
        for (int i = 0; i < 2; i++) {
            int lin = tid + i * 128;
            int tok = lin & 31, kq = lin >> 5;
            Xs[kq * 4 + 0][tok] = xv[i].x;
            Xs[kq * 4 + 1][tok] = xv[i].y;
            Xs[kq * 4 + 2][tok] = xv[i].z;
            Xs[kq * 4 + 3][tok] = xv[i].w;
            Ws[kq * 4 + 0][tok] = wv[i].x;   // tok == expert index here
            Ws[kq * 4 + 1][tok] = wv[i].y;
            Ws[kq * 4 + 2][tok] = wv[i].z;
            Ws[kq * 4 + 3][tok] = wv[i].w;
        }
        __syncthreads();
        if (c < 7) {
            int kq0 = (c + 1) * 8;
#pragma unroll
            for (int i = 0; i < 2; i++) {
                int lin = tid + i * 128;
                xv[i] = Xg[(size_t)(tok0 + (lin & 31)) * 64 + kq0 + (lin >> 5)];
                wv[i] = Wg[(size_t)(lin & 31) * 64 + kq0 + (lin >> 5)];
            }
        }
#pragma unroll
        for (int k = 0; k < 32; k++) {
            u64 a = *(const u64*)&Xs[k][ty * 2];
            float4 b = *(const float4*)&Ws[k][tx * 4];
            u64 bd0, bd1, bd2, bd3;
            DUP2(bd0, b.x); DUP2(bd1, b.y); DUP2(bd2, b.z); DUP2(bd3, b.w);
            FMA2(acc2[0], a, bd0);
            FMA2(acc2[1], a, bd1);
            FMA2(acc2[2], a, bd2);
            FMA2(acc2[3], a, bd3);
        }
        __syncthreads();
    }

    // bias + first-max argmax (strict >, lower-idx ties)
    float4 rbv4 = *(const float4*)&rb[tx * 4];
    float rbv[4] = {rbv4.x, rbv4.y, rbv4.z, rbv4.w};
    float lv[2][4];
#pragma unroll
    for (int j = 0; j < 4; j++) {
        float lo, hi;
        UNPK(lo, hi, acc2[j]);
        lv[0][j] = lo + rbv[j];
        lv[1][j] = hi + rbv[j];
    }
#pragma unroll
    for (int i = 0; i < 2; i++) {
        float v = lv[i][0];
        int idx = tx * 4;
#pragma unroll
        for (int j = 1; j < 4; j++)
            if (lv[i][j] > v) { v = lv[i][j]; idx = tx * 4 + j; }
#pragma unroll
        for (int m = 1; m < 8; m <<= 1) {
            float ov = __shfl_xor_sync(0xffffffffu, v, m);
            int   oi = __shfl_xor_sync(0xffffffffu, idx, m);
            if (ov > v || (ov == v && oi < idx)) { v = ov; idx = oi; }
        }
        if (tx == 0) {
            g_idx[tok0 + ty * 2 + i] = idx;
            atomicAdd(&hist[idx], 1);
        }
    }
    __syncthreads();
    if (tid < NEXP && hist[tid]) atomicAdd(&g_counts[tid], hist[tid]);
}

// ---------------- kernel 2: 32-entry exclusive scan (1 warp) ----------------
__global__ void k_scan() {
    int lane = threadIdx.x;
    int c = g_counts[lane];
    int s = c;
#pragma unroll
    for (int off = 1; off < 32; off <<= 1) {
        int t = __shfl_up_sync(0xffffffffu, s, off);
        if (lane >= off) s += t;
    }
    g_off[lane]    = s - c;
    g_cursor[lane] = s - c;
    if (lane == 31) g_off[NEXP] = s;
    g_counts[lane] = 0;                // ready for next graph replay
}

// ---------------- kernel 3: scatter (block-aggregated counting sort) ----------------
__global__ void __launch_bounds__(256) k_scatter() {
    __shared__ int hist[NEXP], sbase[NEXP], scur[NEXP];
    int tid = threadIdx.x;
    int n = blockIdx.x * 256 + tid;
    int e = g_idx[n];
    if (tid < NEXP) { hist[tid] = 0; scur[tid] = 0; }
    __syncthreads();
    atomicAdd(&hist[e], 1);
    __syncthreads();
    if (tid < NEXP) sbase[tid] = atomicAdd(&g_cursor[tid], hist[tid]);
    __syncthreads();
    int r = atomicAdd(&scur[e], 1);
    g_perm[sbase[e] + r] = n;
}

// ---------------- kernel 4: grouped expert FFN (256 thr, TM=32) ----------------
// 288 CTAs x 256 thr (8 warps) -> 2 CTAs/SM = 16 warps/SM (4/SMSP) for
// latency cover at UNCHANGED tile size and W traffic. Thread tile 2 tok x 4 h
// in f32x2; double-buffered smem arena with reg-prefetch pipeline.
__global__ void __launch_bounds__(256) k_ffn(const float* __restrict__ x,
                                             const float* __restrict__ W1,
                                             const float* __restrict__ b1,
                                             const float* __restrict__ W2,
                                             const float* __restrict__ b2,
                                             float* __restrict__ out) {
    // map blockIdx.x -> (expert e, tile)
    int e = -1, tile = 0;
    {
        int t = blockIdx.x, acc = 0, prev = g_off[0];
#pragma unroll
        for (int ee = 0; ee < NEXP; ee++) {
            int nxt = g_off[ee + 1];
            int tiles_e = (nxt - prev + TM - 1) >> 5;
            if (e < 0 && t < acc + tiles_e) { e = ee; tile = t - acc; }
            acc += tiles_e;
            prev = nxt;
        }
        if (e < 0) return;
    }

    const int off0 = g_off[e];
    const int cnt  = g_off[e + 1] - off0;

    const int tid = threadIdx.x;
    const int tx  = tid & 15;        // 16 h/n-groups of 4
    const int ty  = tid >> 4;        // 16 token-groups of 2

    int rem = cnt - tile * TM;
    const int nt = rem > TM ? TM : rem;

    __shared__ int   toks[TM];
    __shared__ float Hs[HDIM][36];       // [h][tok], padded
    __shared__ float arena[8192];        // 32KB union
#define XS(b,k,t)  arena[(b)*1152 + (k)*36 + (t)]
#define WB1(b,k,h) arena[2304 + (b)*2048 + (k)*64 + (h)]
#define WB2(b,k,nn) arena[(b)*4096 + (k)*64 + (nn)]

    if (tid < TM) toks[tid] = g_perm[off0 + min(tile * TM + tid, cnt - 1)];
    __syncthreads();

    const float4* Xg  = (const float4*)x;
    const float4* Wg1 = (const float4*)(W1 + (size_t)e * DDIM * HDIM);
    const float4* W2g = (const float4*)(W2 + (size_t)e * HDIM * DDIM);

    const int tokA = tid & 31, kqA = (tid >> 5) & 7;   // 32 tok x 8 kq = 256 thr

    float4 xv, wv[2];
    // prologue: prefetch chunk 0
    xv = Xg[(size_t)toks[tokA] * 64 + kqA];
#pragma unroll
    for (int i = 0; i < 2; i++) wv[i] = Wg1[tid + i * 256];

    u64 acc2[4];
#pragma unroll
    for (int j = 0; j < 4; j++) acc2[j] = 0ull;

    // ================= GEMM1: 8 chunks of K=32 =================
    for (int c = 0; c < 8; c++) {
        const int b = c & 1;
        XS(b, kqA * 4 + 0, tokA) = xv.x;
        XS(b, kqA * 4 + 1, tokA) = xv.y;
        XS(b, kqA * 4 + 2, tokA) = xv.z;
        XS(b, kqA * 4 + 3, tokA) = xv.w;
#pragma unroll
        for (int i = 0; i < 2; i++) {
            int lin = tid + i * 256;         // 0..511
            *(float4*)&WB1(b, lin >> 4, (lin & 15) * 4) = wv[i];
        }
        if (c < 7) {
            int k0 = (c + 1) * 32;
            xv = Xg[(size_t)toks[tokA] * 64 + (k0 >> 2) + kqA];
#pragma unroll
            for (int i = 0; i < 2; i++) wv[i] = Wg1[(k0 << 4) + tid + i * 256];
        }
        __syncthreads();
#pragma unroll
        for (int k = 0; k < 32; k++) {
            u64 a = *(const u64*)&XS(b, k, ty * 2);      // 2 tokens packed
            float4 bb = *(const float4*)&WB1(b, k, tx * 4);
            u64 bd0, bd1, bd2, bd3;
            DUP2(bd0, bb.x); DUP2(bd1, bb.y); DUP2(bd2, bb.z); DUP2(bd3, bb.w);
            FMA2(acc2[0], a, bd0);
            FMA2(acc2[1], a, bd1);
            FMA2(acc2[2], a, bd2);
            FMA2(acc2[3], a, bd3);
        }
    }

    // bias + relu -> Hs[h][tok]
    {
        float4 bb = *(const float4*)&b1[e * HDIM + tx * 4];
        float bv[4] = {bb.x, bb.y, bb.z, bb.w};
#pragma unroll
        for (int j = 0; j < 4; j++) {
            float lo, hi;
            UNPK(lo, hi, acc2[j]);
            lo += bv[j]; hi += bv[j];
            Hs[tx * 4 + j][ty * 2 + 0] = lo > 0.f ? lo : 0.f;
            Hs[tx * 4 + j][ty * 2 + 1] = hi > 0.f ? hi : 0.f;
        }
    }

    // ---- GEMM2 prologue: prefetch W2 chunk 0 ----
    float4 wv2[4];
#pragma unroll
    for (int i = 0; i < 4; i++) {
        int lin = tid + i * 256;             // 0..1023
        wv2[i] = W2g[(lin >> 4) * 64 + (lin & 15)];
    }
    __syncthreads();   // GEMM1 arena reads + Hs writes complete

    // ================= GEMM2: 4 chunks of 64 output cols =================
    for (int c = 0; c < 4; c++) {
        const int b = c & 1;
#pragma unroll
        for (int i = 0; i < 4; i++) {
            int lin = tid + i * 256;
            *(float4*)&WB2(b, lin >> 4, (lin & 15) * 4) = wv2[i];
        }
        if (c < 3) {
#pragma unroll
            for (int i = 0; i < 4; i++) {
                int lin = tid + i * 256;
                wv2[i] = W2g[(lin >> 4) * 64 + (c + 1) * 16 + (lin & 15)];
            }
        }
        __syncthreads();

#pragma unroll
        for (int j = 0; j < 4; j++) acc2[j] = 0ull;

#pragma unroll 8
        for (int k = 0; k < HDIM; k++) {
            u64 a = *(const u64*)&Hs[k][ty * 2];
            float4 bb = *(const float4*)&WB2(b, k, tx * 4);
            u64 bd0, bd1, bd2, bd3;
            DUP2(bd0, bb.x); DUP2(bd1, bb.y); DUP2(bd2, bb.z); DUP2(bd3, bb.w);
            FMA2(acc2[0], a, bd0);
            FMA2(acc2[1], a, bd1);
            FMA2(acc2[2], a, bd2);
            FMA2(acc2[3], a, bd3);
        }

        // epilogue: bias + relu + store this 64-col chunk
        float4 cb = *(const float4*)&b2[e * DDIM + c * 64 + tx * 4];
        float cv[4] = {cb.x, cb.y, cb.z, cb.w};
        float r[2][4];
#pragma unroll
        for (int j = 0; j < 4; j++) {
            float lo, hi;
            UNPK(lo, hi, acc2[j]);
            r[0][j] = fmaxf(lo + cv[j], 0.f);
            r[1][j] = fmaxf(hi + cv[j], 0.f);
        }
#pragma unroll
        for (int i = 0; i < 2; i++) {
            int ti = ty * 2 + i;
            if (ti < nt) {
                size_t row = (size_t)toks[ti] * DDIM;
                float4 rv;
                rv.x = r[i][0]; rv.y = r[i][1]; rv.z = r[i][2]; rv.w = r[i][3];
                *(float4*)&out[row + c * 64 + tx * 4] = rv;
            }
        }
    }
#undef XS
#undef WB1
#undef WB2
}

// ---------------- launch ----------------
extern "C" void kernel_launch(void* const* d_in, const int* in_sizes, int n_in,
                              void* d_out, int out_size) {
    const float* x   = (const float*)d_in[0];
    const float* rw  = (const float*)d_in[1];
    const float* rb  = (const float*)d_in[2];
    const float* W1  = (const float*)d_in[3];
    const float* b1  = (const float*)d_in[4];
    const float* W2  = (const float*)d_in[5];
    const float* b2  = (const float*)d_in[6];
    float* out = (float*)d_out;

    k_router<<<N_TOK / 32, 128>>>(x, rw, rb);
    k_scan<<<1, 32>>>();
    k_scatter<<<N_TOK / 256, 256>>>();
    k_ffn<<<FFN_CTAS, 256>>>(x, W1, b1, W2, b2, out);
}

// round 12
// speedup vs baseline: 1.0098x; 1.0098x over previous
#include <cuda_runtime.h>

#define N_TOK 8192
#define DDIM  256
#define HDIM  64
#define NEXP  32
#define TM    64        // tokens per ffn tile
#define FFN_CTAS 160    // max tiles: 8192/64=128 full + <=32 partial tails

typedef unsigned long long u64;

// packed-f32x2 helpers (sm_100+; ptxas never emits FFMA2 from C++)
#define DUP2(d, s)    asm("mov.b64 %0, {%1, %1};" : "=l"(d) : "f"(s))
#define FMA2(c, a, b) asm("fma.rn.f32x2 %0, %1, %2, %0;" : "+l"(c) : "l"(a), "l"(b))
#define UNPK(lo, hi, p) asm("mov.b64 {%0, %1}, %2;" : "=f"(lo), "=f"(hi) : "l"(p))

// ---------------- scratch (no allocations allowed) ----------------
__device__ int g_idx[N_TOK];
__device__ int g_counts[NEXP];     // zero at init; k_scan resets each call
__device__ int g_off[NEXP + 1];
__device__ int g_cursor[NEXP];
__device__ int g_perm[N_TOK];

// ---------------- kernel 1: router GEMM + fused argmax (R9 verbatim) ----------------
__global__ void __launch_bounds__(128) k_router(const float* __restrict__ x,
                                                const float* __restrict__ rw,
                                                const float* __restrict__ rb) {
    const int tid = threadIdx.x;
    const int tx  = tid & 7;
    const int ty  = tid >> 3;
    const int tok0 = blockIdx.x * 32;

    __shared__ float Xs[32][36];
    __shared__ float Ws[32][32];
    __shared__ int   hist[NEXP];

    if (tid < NEXP) hist[tid] = 0;

    const float4* Xg = (const float4*)x;
    const float4* Wg = (const float4*)rw;

    float4 xv[2], wv[2];
#pragma unroll
    for (int i = 0; i < 2; i++) {
        int lin = tid + i * 128;
        xv[i] = Xg[(size_t)(tok0 + (lin & 31)) * 64 + (lin >> 5)];
        wv[i] = Wg[(size_t)(lin & 31) * 64 + (lin >> 5)];
    }

    u64 acc2[4];
#pragma unroll
    for (int j = 0; j < 4; j++) acc2[j] = 0ull;

    for (int c = 0; c < 8; c++) {
#pragma unroll
        for (int i = 0; i < 2; i++) {
            int lin = tid + i * 128;
            int tok = lin & 31, kq = lin >> 5;
            Xs[kq * 4 + 0][tok] = xv[i].x;
            Xs[kq * 4 + 1][tok] = xv[i].y;
            Xs[kq * 4 + 2][tok] = xv[i].z;
            Xs[kq * 4 + 3][tok] = xv[i].w;
            Ws[kq * 4 + 0][tok] = wv[i].x;
            Ws[kq * 4 + 1][tok] = wv[i].y;
            Ws[kq * 4 + 2][tok] = wv[i].z;
            Ws[kq * 4 + 3][tok] = wv[i].w;
        }
        __syncthreads();
        if (c < 7) {
            int kq0 = (c + 1) * 8;
#pragma unroll
            for (int i = 0; i < 2; i++) {
                int lin = tid + i * 128;
                xv[i] = Xg[(size_t)(tok0 + (lin & 31)) * 64 + kq0 + (lin >> 5)];
                wv[i] = Wg[(size_t)(lin & 31) * 64 + kq0 + (lin >> 5)];
            }
        }
#pragma unroll
        for (int k = 0; k < 32; k++) {
            u64 a = *(const u64*)&Xs[k][ty * 2];
            float4 b = *(const float4*)&Ws[k][tx * 4];
            u64 bd0, bd1, bd2, bd3;
            DUP2(bd0, b.x); DUP2(bd1, b.y); DUP2(bd2, b.z); DUP2(bd3, b.w);
            FMA2(acc2[0], a, bd0);
            FMA2(acc2[1], a, bd1);
            FMA2(acc2[2], a, bd2);
            FMA2(acc2[3], a, bd3);
        }
        __syncthreads();
    }

    float4 rbv4 = *(const float4*)&rb[tx * 4];
    float rbv[4] = {rbv4.x, rbv4.y, rbv4.z, rbv4.w};
    float lv[2][4];
#pragma unroll
    for (int j = 0; j < 4; j++) {
        float lo, hi;
        UNPK(lo, hi, acc2[j]);
        lv[0][j] = lo + rbv[j];
        lv[1][j] = hi + rbv[j];
    }
#pragma unroll
    for (int i = 0; i < 2; i++) {
        float v = lv[i][0];
        int idx = tx * 4;
#pragma unroll
        for (int j = 1; j < 4; j++)
            if (lv[i][j] > v) { v = lv[i][j]; idx = tx * 4 + j; }  // first-max
#pragma unroll
        for (int m = 1; m < 8; m <<= 1) {
            float ov = __shfl_xor_sync(0xffffffffu, v, m);
            int   oi = __shfl_xor_sync(0xffffffffu, idx, m);
            if (ov > v || (ov == v && oi < idx)) { v = ov; idx = oi; }
        }
        if (tx == 0) {
            g_idx[tok0 + ty * 2 + i] = idx;
            atomicAdd(&hist[idx], 1);
        }
    }
    __syncthreads();
    if (tid < NEXP && hist[tid]) atomicAdd(&g_counts[tid], hist[tid]);
}

// ---------------- kernel 2: 32-entry exclusive scan (1 warp) ----------------
__global__ void k_scan() {
    int lane = threadIdx.x;
    int c = g_counts[lane];
    int s = c;
#pragma unroll
    for (int off = 1; off < 32; off <<= 1) {
        int t = __shfl_up_sync(0xffffffffu, s, off);
        if (lane >= off) s += t;
    }
    g_off[lane]    = s - c;
    g_cursor[lane] = s - c;
    if (lane == 31) g_off[NEXP] = s;
    g_counts[lane] = 0;
}

// ---------------- kernel 3: scatter (block-aggregated counting sort) ----------------
__global__ void __launch_bounds__(256) k_scatter() {
    __shared__ int hist[NEXP], sbase[NEXP], scur[NEXP];
    int tid = threadIdx.x;
    int n = blockIdx.x * 256 + tid;
    int e = g_idx[n];
    if (tid < NEXP) { hist[tid] = 0; scur[tid] = 0; }
    __syncthreads();
    atomicAdd(&hist[e], 1);
    __syncthreads();
    if (tid < NEXP) sbase[tid] = atomicAdd(&g_cursor[tid], hist[tid]);
    __syncthreads();
    int r = atomicAdd(&scur[e], 1);
    g_perm[sbase[e] + r] = n;
}

// ---------------- kernel 4: grouped expert FFN (TM=64, 4tok x 8h tiles) ----------------
// 160 CTAs x 128 thr. Thread tile 4 tok x 8 h => 3 LDS / 32 MACs (0.094/MAC,
// -25% vs prior 0.125) -- the smem-crossbar bound is the measured limiter.
// Reg-prefetch pipelined, FFMA2 inner loops.
__global__ void __launch_bounds__(128) k_ffn(const float* __restrict__ x,
                                             const float* __restrict__ W1,
                                             const float* __restrict__ b1,
                                             const float* __restrict__ W2,
                                             const float* __restrict__ b2,
                                             float* __restrict__ out) {
    // map blockIdx.x -> (expert e, tile)
    int e = -1, tile = 0;
    {
        int t = blockIdx.x, acc = 0, prev = g_off[0];
#pragma unroll
        for (int ee = 0; ee < NEXP; ee++) {
            int nxt = g_off[ee + 1];
            int tiles_e = (nxt - prev + TM - 1) >> 6;
            if (e < 0 && t < acc + tiles_e) { e = ee; tile = t - acc; }
            acc += tiles_e;
            prev = nxt;
        }
        if (e < 0) return;
    }

    const int off0 = g_off[e];
    const int cnt  = g_off[e + 1] - off0;

    const int tid = threadIdx.x;
    const int tx  = tid & 7;         // 8 h/n-groups of 8
    const int ty  = tid >> 3;        // 16 token-groups of 4

    int rem = cnt - tile * TM;
    const int nt = rem > TM ? TM : rem;

    __shared__ int   toks[TM];
    __shared__ float Hs[HDIM][68];       // [h][tok], padded
    __shared__ float arena[8448];        // 33KB union:
    // GEMM1: XS[b][k][t] (2x32x68) + WB1[b][k][h] (2x32x64)
    // GEMM2: WB2[b][k][n] (2x64x64)
#define XS(b,k,t)   arena[(b)*2176 + (k)*68 + (t)]
#define WB1(b,k,h)  arena[4352 + (b)*2048 + (k)*64 + (h)]
#define WB2(b,k,nn) arena[(b)*4096 + (k)*64 + (nn)]

    if (tid < TM) toks[tid] = g_perm[off0 + min(tile * TM + tid, cnt - 1)];
    __syncthreads();

    const float4* Xg  = (const float4*)x;
    const float4* Wg1 = (const float4*)(W1 + (size_t)e * DDIM * HDIM);
    const float4* W2g = (const float4*)(W2 + (size_t)e * HDIM * DDIM);

    float4 xv[4], wv[4];
    // prologue: prefetch chunk 0 (X: 64 tok x 8 kq = 512 f4; W1: 512 f4)
#pragma unroll
    for (int i = 0; i < 4; i++) {
        int lin = tid + i * 128;
        xv[i] = Xg[(size_t)toks[lin & 63] * 64 + (lin >> 6)];
        wv[i] = Wg1[lin];
    }

    u64 acc2[2][8];
#pragma unroll
    for (int p = 0; p < 2; p++)
#pragma unroll
        for (int j = 0; j < 8; j++) acc2[p][j] = 0ull;

    // ================= GEMM1: 8 chunks of K=32 =================
    for (int c = 0; c < 8; c++) {
        const int b = c & 1;
#pragma unroll
        for (int i = 0; i < 4; i++) {
            int lin = tid + i * 128;
            int tok = lin & 63, kq = lin >> 6;
            XS(b, kq * 4 + 0, tok) = xv[i].x;
            XS(b, kq * 4 + 1, tok) = xv[i].y;
            XS(b, kq * 4 + 2, tok) = xv[i].z;
            XS(b, kq * 4 + 3, tok) = xv[i].w;
            *(float4*)&WB1(b, lin >> 4, (lin & 15) * 4) = wv[i];
        }
        if (c < 7) {
            int k0 = (c + 1) * 32;
#pragma unroll
            for (int i = 0; i < 4; i++) {
                int lin = tid + i * 128;
                xv[i] = Xg[(size_t)toks[lin & 63] * 64 + (k0 >> 2) + (lin >> 6)];
                wv[i] = Wg1[(k0 << 4) + lin];
            }
        }
        __syncthreads();
#pragma unroll
        for (int k = 0; k < 32; k++) {
            ulonglong2 a = *(const ulonglong2*)&XS(b, k, ty * 4);
            float4 b0 = *(const float4*)&WB1(b, k, tx * 8);
            float4 b1v = *(const float4*)&WB1(b, k, tx * 8 + 4);
            u64 bd;
            DUP2(bd, b0.x); FMA2(acc2[0][0], a.x, bd); FMA2(acc2[1][0], a.y, bd);
            DUP2(bd, b0.y); FMA2(acc2[0][1], a.x, bd); FMA2(acc2[1][1], a.y, bd);
            DUP2(bd, b0.z); FMA2(acc2[0][2], a.x, bd); FMA2(acc2[1][2], a.y, bd);
            DUP2(bd, b0.w); FMA2(acc2[0][3], a.x, bd); FMA2(acc2[1][3], a.y, bd);
            DUP2(bd, b1v.x); FMA2(acc2[0][4], a.x, bd); FMA2(acc2[1][4], a.y, bd);
            DUP2(bd, b1v.y); FMA2(acc2[0][5], a.x, bd); FMA2(acc2[1][5], a.y, bd);
            DUP2(bd, b1v.z); FMA2(acc2[0][6], a.x, bd); FMA2(acc2[1][6], a.y, bd);
            DUP2(bd, b1v.w); FMA2(acc2[0][7], a.x, bd); FMA2(acc2[1][7], a.y, bd);
        }
    }

    // bias + relu -> Hs[h][tok] (pairwise STS.64; one-time transpose)
    {
        float4 bb0 = *(const float4*)&b1[e * HDIM + tx * 8];
        float4 bb1 = *(const float4*)&b1[e * HDIM + tx * 8 + 4];
        float bv[8] = {bb0.x, bb0.y, bb0.z, bb0.w, bb1.x, bb1.y, bb1.z, bb1.w};
#pragma unroll
        for (int p = 0; p < 2; p++) {
#pragma unroll
            for (int j = 0; j < 8; j++) {
                float lo, hi;
                UNPK(lo, hi, acc2[p][j]);
                lo += bv[j]; hi += bv[j];
                float2 hv;
                hv.x = lo > 0.f ? lo : 0.f;
                hv.y = hi > 0.f ? hi : 0.f;
                *(float2*)&Hs[tx * 8 + j][ty * 4 + 2 * p] = hv;
            }
        }
    }

    // ---- GEMM2 prologue: prefetch W2 chunk 0 (64 cols: 1024 f4) ----
    float4 wv2[8];
#pragma unroll
    for (int i = 0; i < 8; i++) {
        int lin = tid + i * 128;
        wv2[i] = W2g[(lin >> 4) * 64 + (lin & 15)];
    }
    __syncthreads();   // GEMM1 arena reads + Hs writes complete

    // ================= GEMM2: 4 chunks of 64 output cols =================
    for (int c = 0; c < 4; c++) {
        const int b = c & 1;
#pragma unroll
        for (int i = 0; i < 8; i++) {
            int lin = tid + i * 128;
            *(float4*)&WB2(b, lin >> 4, (lin & 15) * 4) = wv2[i];
        }
        if (c < 3) {
#pragma unroll
            for (int i = 0; i < 8; i++) {
                int lin = tid + i * 128;
                wv2[i] = W2g[(lin >> 4) * 64 + (c + 1) * 16 + (lin & 15)];
            }
        }
        __syncthreads();

#pragma unroll
        for (int p = 0; p < 2; p++)
#pragma unroll
            for (int j = 0; j < 8; j++) acc2[p][j] = 0ull;

#pragma unroll 8
        for (int k = 0; k < HDIM; k++) {
            ulonglong2 a = *(const ulonglong2*)&Hs[k][ty * 4];
            float4 b0 = *(const float4*)&WB2(b, k, tx * 8);
            float4 b1v = *(const float4*)&WB2(b, k, tx * 8 + 4);
            u64 bd;
            DUP2(bd, b0.x); FMA2(acc2[0][0], a.x, bd); FMA2(acc2[1][0], a.y, bd);
            DUP2(bd, b0.y); FMA2(acc2[0][1], a.x, bd); FMA2(acc2[1][1], a.y, bd);
            DUP2(bd, b0.z); FMA2(acc2[0][2], a.x, bd); FMA2(acc2[1][2], a.y, bd);
            DUP2(bd, b0.w); FMA2(acc2[0][3], a.x, bd); FMA2(acc2[1][3], a.y, bd);
            DUP2(bd, b1v.x); FMA2(acc2[0][4], a.x, bd); FMA2(acc2[1][4], a.y, bd);
            DUP2(bd, b1v.y); FMA2(acc2[0][5], a.x, bd); FMA2(acc2[1][5], a.y, bd);
            DUP2(bd, b1v.z); FMA2(acc2[0][6], a.x, bd); FMA2(acc2[1][6], a.y, bd);
            DUP2(bd, b1v.w); FMA2(acc2[0][7], a.x, bd); FMA2(acc2[1][7], a.y, bd);
        }

        // epilogue: bias + relu + store this 64-col chunk
        float4 cb0 = *(const float4*)&b2[e * DDIM + c * 64 + tx * 8];
        float4 cb1 = *(const float4*)&b2[e * DDIM + c * 64 + tx * 8 + 4];
        float cv[8] = {cb0.x, cb0.y, cb0.z, cb0.w, cb1.x, cb1.y, cb1.z, cb1.w};
        float r[4][8];
#pragma unroll
        for (int p = 0; p < 2; p++) {
#pragma unroll
            for (int j = 0; j < 8; j++) {
                float lo, hi;
                UNPK(lo, hi, acc2[p][j]);
                r[2 * p][j]     = fmaxf(lo + cv[j], 0.f);
                r[2 * p + 1][j] = fmaxf(hi + cv[j], 0.f);
            }
        }
#pragma unroll
        for (int i = 0; i < 4; i++) {
            int ti = ty * 4 + i;
            if (ti < nt) {
                size_t row = (size_t)toks[ti] * DDIM;
                float4 r0, r1;
                r0.x = r[i][0]; r0.y = r[i][1]; r0.z = r[i][2]; r0.w = r[i][3];
                r1.x = r[i][4]; r1.y = r[i][5]; r1.z = r[i][6]; r1.w = r[i][7];
                *(float4*)&out[row + c * 64 + tx * 8] = r0;
                *(float4*)&out[row + c * 64 + tx * 8 + 4] = r1;
            }
        }
    }
#undef XS
#undef WB1
#undef WB2
}

// ---------------- launch ----------------
extern "C" void kernel_launch(void* const* d_in, const int* in_sizes, int n_in,
                              void* d_out, int out_size) {
    const float* x   = (const float*)d_in[0];
    const float* rw  = (const float*)d_in[1];
    const float* rb  = (const float*)d_in[2];
    const float* W1  = (const float*)d_in[3];
    const float* b1  = (const float*)d_in[4];
    const float* W2  = (const float*)d_in[5];
    const float* b2  = (const float*)d_in[6];
    float* out = (float*)d_out;

    k_router<<<N_TOK / 32, 128>>>(x, rw, rb);
    k_scan<<<1, 32>>>();
    k_scatter<<<N_TOK / 256, 256>>>();
    k_ffn<<<FFN_CTAS, 128>>>(x, W1, b1, W2, b2, out);
}

// round 14
// speedup vs baseline: 1.2524x; 1.2402x over previous
#include <cuda_runtime.h>
#include <cstdint>

#define N_TOK 8192
#define DDIM  256
#define HDIM  64
#define NEXP  32
#define TM    32        // tokens per ffn tile
#define FFN_CTAS 288    // >= max tiles: 8192/32=256 full + <=31 partial tails

typedef unsigned long long u64;
typedef unsigned int u32;

// packed-f32x2 helpers (sm_100+; ptxas never emits FFMA2 from C++)
#define DUP2(d, s)    asm("mov.b64 %0, {%1, %1};" : "=l"(d) : "f"(s))
#define FMA2(c, a, b) asm("fma.rn.f32x2 %0, %1, %2, %0;" : "+l"(c) : "l"(a), "l"(b))
#define UNPK(lo, hi, p) asm("mov.b64 {%0, %1}, %2;" : "=f"(lo), "=f"(hi) : "l"(p))

// cp.async 16B, L2-only (streaming weights)
#define CPA16(dst_u32, src_ptr) \
    asm volatile("cp.async.cg.shared.global [%0], [%1], 16;" :: "r"(dst_u32), "l"(src_ptr))
#define CPA_COMMIT()  asm volatile("cp.async.commit_group;")
#define CPA_WAIT0()   asm volatile("cp.async.wait_group 0;")

// ---------------- scratch (no allocations allowed) ----------------
__device__ int g_idx[N_TOK];
__device__ int g_counts[NEXP];     // zero at init; k_scan resets each call
__device__ int g_off[NEXP + 1];
__device__ int g_cursor[NEXP];
__device__ int g_perm[N_TOK];

// ---------------- kernel 1: router GEMM + fused argmax (R7 config) ----------------
// 128 CTAs x 128 thr; CTA tile 64 tok x 32 exp; K pipelined via reg prefetch.
__global__ void __launch_bounds__(128) k_router(const float* __restrict__ x,
                                                const float* __restrict__ rw,
                                                const float* __restrict__ rb) {
    const int tid = threadIdx.x;
    const int tx  = tid & 7;
    const int ty  = tid >> 3;
    const int tok0 = blockIdx.x * 64;

    __shared__ float Xs[32][68];
    __shared__ float Ws[32][32];
    __shared__ int   hist[NEXP];

    if (tid < NEXP) hist[tid] = 0;

    const float4* Xg = (const float4*)x;
    const float4* Wg = (const float4*)rw;

    float4 xv[4], wv[2];
#pragma unroll
    for (int i = 0; i < 4; i++) {
        int lin = tid + i * 128;
        xv[i] = Xg[(size_t)(tok0 + (lin & 63)) * 64 + (lin >> 6)];
    }
#pragma unroll
    for (int i = 0; i < 2; i++) {
        int lin = tid + i * 128;
        wv[i] = Wg[(size_t)(lin & 31) * 64 + (lin >> 5)];
    }

    float acc[4][4];
#pragma unroll
    for (int i = 0; i < 4; i++)
#pragma unroll
        for (int j = 0; j < 4; j++) acc[i][j] = 0.f;

    for (int c = 0; c < 8; c++) {
#pragma unroll
        for (int i = 0; i < 4; i++) {
            int lin = tid + i * 128;
            int tok = lin & 63, kq = lin >> 6;
            Xs[kq * 4 + 0][tok] = xv[i].x;
            Xs[kq * 4 + 1][tok] = xv[i].y;
            Xs[kq * 4 + 2][tok] = xv[i].z;
            Xs[kq * 4 + 3][tok] = xv[i].w;
        }
#pragma unroll
        for (int i = 0; i < 2; i++) {
            int lin = tid + i * 128;
            int ee = lin & 31, kq = lin >> 5;
            Ws[kq * 4 + 0][ee] = wv[i].x;
            Ws[kq * 4 + 1][ee] = wv[i].y;
            Ws[kq * 4 + 2][ee] = wv[i].z;
            Ws[kq * 4 + 3][ee] = wv[i].w;
        }
        __syncthreads();
        if (c < 7) {
            int kq0 = (c + 1) * 8;
#pragma unroll
            for (int i = 0; i < 4; i++) {
                int lin = tid + i * 128;
                xv[i] = Xg[(size_t)(tok0 + (lin & 63)) * 64 + kq0 + (lin >> 6)];
            }
#pragma unroll
            for (int i = 0; i < 2; i++) {
                int lin = tid + i * 128;
                wv[i] = Wg[(size_t)(lin & 31) * 64 + kq0 + (lin >> 5)];
            }
        }
#pragma unroll
        for (int k = 0; k < 32; k++) {
            float4 a = *(const float4*)&Xs[k][ty * 4];
            float4 b = *(const float4*)&Ws[k][tx * 4];
            float av[4] = {a.x, a.y, a.z, a.w};
            float bv[4] = {b.x, b.y, b.z, b.w};
#pragma unroll
            for (int i = 0; i < 4; i++)
#pragma unroll
                for (int j = 0; j < 4; j++) acc[i][j] += av[i] * bv[j];
        }
        __syncthreads();
    }

    float4 rbv4 = *(const float4*)&rb[tx * 4];
    float rbv[4] = {rbv4.x, rbv4.y, rbv4.z, rbv4.w};
#pragma unroll
    for (int i = 0; i < 4; i++) {
        float v = acc[i][0] + rbv[0];
        int idx = tx * 4;
#pragma unroll
        for (int j = 1; j < 4; j++) {
            float val = acc[i][j] + rbv[j];
            if (val > v) { v = val; idx = tx * 4 + j; }   // strict > = first-max
        }
#pragma unroll
        for (int m = 1; m < 8; m <<= 1) {
            float ov = __shfl_xor_sync(0xffffffffu, v, m);
            int   oi = __shfl_xor_sync(0xffffffffu, idx, m);
            if (ov > v || (ov == v && oi < idx)) { v = ov; idx = oi; }
        }
        if (tx == 0) {
            g_idx[tok0 + ty * 4 + i] = idx;
            atomicAdd(&hist[idx], 1);
        }
    }
    __syncthreads();
    if (tid < NEXP && hist[tid]) atomicAdd(&g_counts[tid], hist[tid]);
}

// ---------------- kernel 2: 32-entry exclusive scan (1 warp) ----------------
__global__ void k_scan() {
    int lane = threadIdx.x;
    int c = g_counts[lane];
    int s = c;
#pragma unroll
    for (int off = 1; off < 32; off <<= 1) {
        int t = __shfl_up_sync(0xffffffffu, s, off);
        if (lane >= off) s += t;
    }
    g_off[lane]    = s - c;
    g_cursor[lane] = s - c;
    if (lane == 31) g_off[NEXP] = s;
    g_counts[lane] = 0;
}

// ---------------- kernel 3: scatter (block-aggregated counting sort) ----------------
__global__ void __launch_bounds__(256) k_scatter() {
    __shared__ int hist[NEXP], sbase[NEXP], scur[NEXP];
    int tid = threadIdx.x;
    int n = blockIdx.x * 256 + tid;
    int e = g_idx[n];
    if (tid < NEXP) { hist[tid] = 0; scur[tid] = 0; }
    __syncthreads();
    atomicAdd(&hist[e], 1);
    __syncthreads();
    if (tid < NEXP) sbase[tid] = atomicAdd(&g_cursor[tid], hist[tid]);
    __syncthreads();
    int r = atomicAdd(&scur[e], 1);
    g_perm[sbase[e] + r] = n;
}

// ---------------- kernel 4: grouped expert FFN (cp.async, W2-resident) ----------------
// 288 CTAs x 128 thr (2 CTAs/SM @ 98KB dynamic smem). W1 chunks + W2 slices
// stream via cp.async (no reg prefetch for weights). The FULL 64KB W2 tile is
// resident before GEMM2 -> GEMM2 = 256 barrier-free k-iterations.
// smem layout (bytes): [0,128) toks | [128,9344) Hs[64][36]
//   | [9344,18560) XS 2x32x36 | [18560,34944) WB1 2x32x64 | [34944,100480) W2s 64x256
__global__ void __launch_bounds__(128) k_ffn(const float* __restrict__ x,
                                             const float* __restrict__ W1,
                                             const float* __restrict__ b1,
                                             const float* __restrict__ W2,
                                             const float* __restrict__ b2,
                                             float* __restrict__ out) {
    extern __shared__ __align__(16) char smem[];
    int*   toks = (int*)smem;
    float* Hs   = (float*)(smem + 128);
    float* XSb  = (float*)(smem + 9344);
    float* WB1b = (float*)(smem + 18560);
    float* W2s  = (float*)(smem + 34944);
#define XS(b,k,t)  XSb[(b)*1152 + (k)*36 + (t)]
#define WB1(b,k,h) WB1b[(b)*2048 + (k)*64 + (h)]

    u32 smem_base;
    asm("{ .reg .u64 t; cvta.to.shared.u64 t, %1; cvt.u32.u64 %0, t; }"
        : "=r"(smem_base) : "l"(smem));
    const u32 wb1_u32 = smem_base + 18560;
    const u32 w2s_u32 = smem_base + 34944;

    // map blockIdx.x -> (expert e, tile)
    int e = -1, tile = 0;
    {
        int t = blockIdx.x, acc = 0, prev = g_off[0];
#pragma unroll
        for (int ee = 0; ee < NEXP; ee++) {
            int nxt = g_off[ee + 1];
            int tiles_e = (nxt - prev + TM - 1) >> 5;
            if (e < 0 && t < acc + tiles_e) { e = ee; tile = t - acc; }
            acc += tiles_e;
            prev = nxt;
        }
        if (e < 0) return;
    }

    const int off0 = g_off[e];
    const int cnt  = g_off[e + 1] - off0;

    const int tid = threadIdx.x;
    const int tx  = tid & 15;        // 16 h/n-groups of 4
    const int ty  = tid >> 4;        // 8 token-groups of 4

    int rem = cnt - tile * TM;
    const int nt = rem > TM ? TM : rem;

    if (tid < TM) toks[tid] = g_perm[off0 + min(tile * TM + tid, cnt - 1)];
    __syncthreads();

    const float4* Xg   = (const float4*)x;
    const float*  W1e  = W1 + (size_t)e * DDIM * HDIM;
    const float*  W2e  = W2 + (size_t)e * HDIM * DDIM;

    const int tokA = tid & 31, kqA = tid >> 5;
    const int tokB = tokA,     kqB = kqA + 4;

    // ---- prologue: X chunk0 reg prefetch + cp.async W1 chunk0 / W2 slice0 ----
    float4 xv0 = Xg[(size_t)toks[tokA] * 64 + kqA];
    float4 xv1 = Xg[(size_t)toks[tokB] * 64 + kqB];
#pragma unroll
    for (int i = 0; i < 4; i++) {
        int f4 = tid + i * 128;                 // 0..511
        CPA16(wb1_u32 + f4 * 16, W1e + f4 * 4);               // W1 chunk0 -> buf0
        CPA16(w2s_u32 + f4 * 16, W2e + f4 * 4);               // W2 slice0
    }
    CPA_COMMIT();

    u64 acc2[2][4];
#pragma unroll
    for (int p = 0; p < 2; p++)
#pragma unroll
        for (int j = 0; j < 4; j++) acc2[p][j] = 0ull;

    // ================= GEMM1: 8 chunks of K=32 =================
    for (int c = 0; c < 8; c++) {
        const int b = c & 1;
        // STS X chunk c (prefetched regs)
        XS(b, kqA * 4 + 0, tokA) = xv0.x;
        XS(b, kqA * 4 + 1, tokA) = xv0.y;
        XS(b, kqA * 4 + 2, tokA) = xv0.z;
        XS(b, kqA * 4 + 3, tokA) = xv0.w;
        XS(b, kqB * 4 + 0, tokB) = xv1.x;
        XS(b, kqB * 4 + 1, tokB) = xv1.y;
        XS(b, kqB * 4 + 2, tokB) = xv1.z;
        XS(b, kqB * 4 + 3, tokB) = xv1.w;
        // prefetch X chunk c+1 (overlaps the cp.async wait)
        if (c < 7) {
            int k0 = (c + 1) * 32;
            xv0 = Xg[(size_t)toks[tokA] * 64 + (k0 >> 2) + kqA];
            xv1 = Xg[(size_t)toks[tokB] * 64 + (k0 >> 2) + kqB];
        }
        CPA_WAIT0();              // W1 chunk c (+W2 slice c) resident
        __syncthreads();
        // issue next chunk's weight streams AFTER the barrier (no WAR race:
        // all warps are now past compute(c-1), the only reader of buf (c+1)&1)
        if (c < 7) {
#pragma unroll
            for (int i = 0; i < 4; i++) {
                int f4 = tid + i * 128;
                CPA16(wb1_u32 + ((c + 1) & 1) * 8192 + f4 * 16,
                      W1e + (c + 1) * 2048 + f4 * 4);
                CPA16(w2s_u32 + (c + 1) * 8192 + f4 * 16,
                      W2e + (c + 1) * 2048 + f4 * 4);
            }
            CPA_COMMIT();
        }
        // compute chunk c
#pragma unroll
        for (int k = 0; k < 32; k++) {
            ulonglong2 a = *(const ulonglong2*)&XS(b, k, ty * 4);
            float4 bb = *(const float4*)&WB1(b, k, tx * 4);
            u64 bd0, bd1, bd2, bd3;
            DUP2(bd0, bb.x); DUP2(bd1, bb.y); DUP2(bd2, bb.z); DUP2(bd3, bb.w);
            FMA2(acc2[0][0], a.x, bd0); FMA2(acc2[1][0], a.y, bd0);
            FMA2(acc2[0][1], a.x, bd1); FMA2(acc2[1][1], a.y, bd1);
            FMA2(acc2[0][2], a.x, bd2); FMA2(acc2[1][2], a.y, bd2);
            FMA2(acc2[0][3], a.x, bd3); FMA2(acc2[1][3], a.y, bd3);
        }
    }

    // bias + relu -> Hs[h][tok]
    {
        float4 bb = *(const float4*)&b1[e * HDIM + tx * 4];
        float bv[4] = {bb.x, bb.y, bb.z, bb.w};
#pragma unroll
        for (int p = 0; p < 2; p++) {
#pragma unroll
            for (int j = 0; j < 4; j++) {
                float lo, hi;
                UNPK(lo, hi, acc2[p][j]);
                lo += bv[j]; hi += bv[j];
                Hs[(tx * 4 + j) * 36 + ty * 4 + 2 * p]     = lo > 0.f ? lo : 0.f;
                Hs[(tx * 4 + j) * 36 + ty * 4 + 2 * p + 1] = hi > 0.f ? hi : 0.f;
            }
        }
    }
    __syncthreads();   // Hs complete; all W2 slices landed (last waited at c=7)

    // ================= GEMM2: 4 chunks of 64 cols, ZERO staging/barriers ======
    for (int c = 0; c < 4; c++) {
#pragma unroll
        for (int p = 0; p < 2; p++)
#pragma unroll
            for (int j = 0; j < 4; j++) acc2[p][j] = 0ull;

#pragma unroll 16
        for (int k = 0; k < HDIM; k++) {
            ulonglong2 a = *(const ulonglong2*)&Hs[k * 36 + ty * 4];
            float4 bb = *(const float4*)&W2s[k * 256 + c * 64 + tx * 4];
            u64 bd0, bd1, bd2, bd3;
            DUP2(bd0, bb.x); DUP2(bd1, bb.y); DUP2(bd2, bb.z); DUP2(bd3, bb.w);
            FMA2(acc2[0][0], a.x, bd0); FMA2(acc2[1][0], a.y, bd0);
            FMA2(acc2[0][1], a.x, bd1); FMA2(acc2[1][1], a.y, bd1);
            FMA2(acc2[0][2], a.x, bd2); FMA2(acc2[1][2], a.y, bd2);
            FMA2(acc2[0][3], a.x, bd3); FMA2(acc2[1][3], a.y, bd3);
        }

        float4 cb = *(const float4*)&b2[e * DDIM + c * 64 + tx * 4];
        float cv[4] = {cb.x, cb.y, cb.z, cb.w};
        float r[4][4];
#pragma unroll
        for (int p = 0; p < 2; p++) {
#pragma unroll
            for (int j = 0; j < 4; j++) {
                float lo, hi;
                UNPK(lo, hi, acc2[p][j]);
                r[2 * p][j]     = fmaxf(lo + cv[j], 0.f);
                r[2 * p + 1][j] = fmaxf(hi + cv[j], 0.f);
            }
        }
#pragma unroll
        for (int i = 0; i < 4; i++) {
            int ti = ty * 4 + i;
            if (ti < nt) {
                size_t row = (size_t)toks[ti] * DDIM;
                float4 rv;
                rv.x = r[i][0]; rv.y = r[i][1]; rv.z = r[i][2]; rv.w = r[i][3];
                *(float4*)&out[row + c * 64 + tx * 4] = rv;
            }
        }
    }
#undef XS
#undef WB1
}

// ---------------- launch ----------------
#define FFN_SMEM 100480

extern "C" void kernel_launch(void* const* d_in, const int* in_sizes, int n_in,
                              void* d_out, int out_size) {
    const float* x   = (const float*)d_in[0];
    const float* rw  = (const float*)d_in[1];
    const float* rb  = (const float*)d_in[2];
    const float* W1  = (const float*)d_in[3];
    const float* b1  = (const float*)d_in[4];
    const float* W2  = (const float*)d_in[5];
    const float* b2  = (const float*)d_in[6];
    float* out = (float*)d_out;

    cudaFuncSetAttribute(k_ffn, cudaFuncAttributeMaxDynamicSharedMemorySize, FFN_SMEM);

    k_router<<<N_TOK / 64, 128>>>(x, rw, rb);
    k_scan<<<1, 32>>>();
    k_scatter<<<N_TOK / 256, 256>>>();
    k_ffn<<<FFN_CTAS, 128, FFN_SMEM>>>(x, W1, b1, W2, b2, out);
}

// round 15
// speedup vs baseline: 1.3168x; 1.0514x over previous
#include <cuda_runtime.h>
#include <cstdint>

#define N_TOK 8192
#define DDIM  256
#define HDIM  64
#define NEXP  32
#define TM    32        // tokens per ffn tile
#define FFN_CTAS 288    // >= max tiles: 8192/32=256 full + <=31 partial tails

typedef unsigned long long u64;
typedef unsigned int u32;

// packed-f32x2 helpers (sm_100+; ptxas never emits FFMA2 from C++)
#define DUP2(d, s)    asm("mov.b64 %0, {%1, %1};" : "=l"(d) : "f"(s))
#define FMA2(c, a, b) asm("fma.rn.f32x2 %0, %1, %2, %0;" : "+l"(c) : "l"(a), "l"(b))
#define UNPK(lo, hi, p) asm("mov.b64 {%0, %1}, %2;" : "=f"(lo), "=f"(hi) : "l"(p))

// cp.async 16B, L2-only (streaming weights)
#define CPA16(dst_u32, src_ptr) \
    asm volatile("cp.async.cg.shared.global [%0], [%1], 16;" :: "r"(dst_u32), "l"(src_ptr))
#define CPA_COMMIT()  asm volatile("cp.async.commit_group;")
#define CPA_WAIT0()   asm volatile("cp.async.wait_group 0;")

// ---------------- scratch (no allocations allowed) ----------------
__device__ int g_idx[N_TOK];
__device__ int g_counts[NEXP];     // zero at init; k_scan resets each call
__device__ int g_off[NEXP + 1];
__device__ int g_cursor[NEXP];
__device__ int g_perm[N_TOK];

// ---------------- kernel 1: router GEMM + fused argmax ----------------
// 256 CTAs x 128 thr (~2 CTAs/SM). CTA tile: 32 tok x 32 exp, K=256 pipelined.
// Scalar thread tile 2 tok x 4 exp: 2 LDS + 8 FFMA per k (no MOV duplication).
__global__ void __launch_bounds__(128) k_router(const float* __restrict__ x,
                                                const float* __restrict__ rw,
                                                const float* __restrict__ rb) {
    const int tid = threadIdx.x;
    const int tx  = tid & 7;       // expert group: experts tx*4..tx*4+3
    const int ty  = tid >> 3;      // token group: tokens 2ty, 2ty+1
    const int tok0 = blockIdx.x * 32;

    __shared__ float Xs[32][36];   // [k][tok]
    __shared__ float Ws[32][32];   // [k][exp]
    __shared__ int   hist[NEXP];

    if (tid < NEXP) hist[tid] = 0;

    const float4* Xg = (const float4*)x;
    const float4* Wg = (const float4*)rw;

    // prefetch chunk 0 (X: 256 f4, W: 256 f4; 128 thr x 2 each)
    float4 xv[2], wv[2];
#pragma unroll
    for (int i = 0; i < 2; i++) {
        int lin = tid + i * 128;            // 0..255: row=lin&31, kq=lin>>5
        xv[i] = Xg[(size_t)(tok0 + (lin & 31)) * 64 + (lin >> 5)];
        wv[i] = Wg[(size_t)(lin & 31) * 64 + (lin >> 5)];
    }

    float acc[2][4];
#pragma unroll
    for (int i = 0; i < 2; i++)
#pragma unroll
        for (int j = 0; j < 4; j++) acc[i][j] = 0.f;

    for (int c = 0; c < 8; c++) {
        // STS prefetched chunk (transposed)
#pragma unroll
        for (int i = 0; i < 2; i++) {
            int lin = tid + i * 128;
            int row = lin & 31, kq = lin >> 5;
            Xs[kq * 4 + 0][row] = xv[i].x;
            Xs[kq * 4 + 1][row] = xv[i].y;
            Xs[kq * 4 + 2][row] = xv[i].z;
            Xs[kq * 4 + 3][row] = xv[i].w;
            Ws[kq * 4 + 0][row] = wv[i].x;   // row == expert index here
            Ws[kq * 4 + 1][row] = wv[i].y;
            Ws[kq * 4 + 2][row] = wv[i].z;
            Ws[kq * 4 + 3][row] = wv[i].w;
        }
        __syncthreads();
        // prefetch chunk c+1
        if (c < 7) {
            int kq0 = (c + 1) * 8;
#pragma unroll
            for (int i = 0; i < 2; i++) {
                int lin = tid + i * 128;
                xv[i] = Xg[(size_t)(tok0 + (lin & 31)) * 64 + kq0 + (lin >> 5)];
                wv[i] = Wg[(size_t)(lin & 31) * 64 + kq0 + (lin >> 5)];
            }
        }
        // compute chunk c: scalar, 2 LDS + 8 FFMA per k
#pragma unroll
        for (int k = 0; k < 32; k++) {
            float2 a = *(const float2*)&Xs[k][ty * 2];
            float4 b = *(const float4*)&Ws[k][tx * 4];
            acc[0][0] += a.x * b.x;  acc[1][0] += a.y * b.x;
            acc[0][1] += a.x * b.y;  acc[1][1] += a.y * b.y;
            acc[0][2] += a.x * b.z;  acc[1][2] += a.y * b.z;
            acc[0][3] += a.x * b.w;  acc[1][3] += a.y * b.w;
        }
        __syncthreads();
    }

    // epilogue: bias + first-max argmax (strict >, lower-idx ties)
    float4 rbv4 = *(const float4*)&rb[tx * 4];
    float rbv[4] = {rbv4.x, rbv4.y, rbv4.z, rbv4.w};
#pragma unroll
    for (int i = 0; i < 2; i++) {
        float v = acc[i][0] + rbv[0];
        int idx = tx * 4;
#pragma unroll
        for (int j = 1; j < 4; j++) {
            float val = acc[i][j] + rbv[j];
            if (val > v) { v = val; idx = tx * 4 + j; }
        }
        // reduce across the 8 expert-lanes (xor m<8 stays in token group)
#pragma unroll
        for (int m = 1; m < 8; m <<= 1) {
            float ov = __shfl_xor_sync(0xffffffffu, v, m);
            int   oi = __shfl_xor_sync(0xffffffffu, idx, m);
            if (ov > v || (ov == v && oi < idx)) { v = ov; idx = oi; }
        }
        if (tx == 0) {
            g_idx[tok0 + ty * 2 + i] = idx;
            atomicAdd(&hist[idx], 1);
        }
    }
    __syncthreads();
    if (tid < NEXP && hist[tid]) atomicAdd(&g_counts[tid], hist[tid]);
}

// ---------------- kernel 2: 32-entry exclusive scan (1 warp) ----------------
__global__ void k_scan() {
    int lane = threadIdx.x;
    int c = g_counts[lane];
    int s = c;
#pragma unroll
    for (int off = 1; off < 32; off <<= 1) {
        int t = __shfl_up_sync(0xffffffffu, s, off);
        if (lane >= off) s += t;
    }
    g_off[lane]    = s - c;
    g_cursor[lane] = s - c;
    if (lane == 31) g_off[NEXP] = s;
    g_counts[lane] = 0;
}

// ---------------- kernel 3: scatter (block-aggregated counting sort) ----------------
__global__ void __launch_bounds__(256) k_scatter() {
    __shared__ int hist[NEXP], sbase[NEXP], scur[NEXP];
    int tid = threadIdx.x;
    int n = blockIdx.x * 256 + tid;
    int e = g_idx[n];
    if (tid < NEXP) { hist[tid] = 0; scur[tid] = 0; }
    __syncthreads();
    atomicAdd(&hist[e], 1);
    __syncthreads();
    if (tid < NEXP) sbase[tid] = atomicAdd(&g_cursor[tid], hist[tid]);
    __syncthreads();
    int r = atomicAdd(&scur[e], 1);
    g_perm[sbase[e] + r] = n;
}

// ---------------- kernel 4: grouped expert FFN (R14 verbatim) ----------------
// 288 CTAs x 128 thr (2 CTAs/SM @ 98KB dynamic smem). W1 chunks + W2 slices
// stream via cp.async. FULL 64KB W2 tile resident before GEMM2.
__global__ void __launch_bounds__(128) k_ffn(const float* __restrict__ x,
                                             const float* __restrict__ W1,
                                             const float* __restrict__ b1,
                                             const float* __restrict__ W2,
                                             const float* __restrict__ b2,
                                             float* __restrict__ out) {
    extern __shared__ __align__(16) char smem[];
    int*   toks = (int*)smem;
    float* Hs   = (float*)(smem + 128);
    float* XSb  = (float*)(smem + 9344);
    float* WB1b = (float*)(smem + 18560);
    float* W2s  = (float*)(smem + 34944);
#define XS(b,k,t)  XSb[(b)*1152 + (k)*36 + (t)]
#define WB1(b,k,h) WB1b[(b)*2048 + (k)*64 + (h)]

    u32 smem_base;
    asm("{ .reg .u64 t; cvta.to.shared.u64 t, %1; cvt.u32.u64 %0, t; }"
        : "=r"(smem_base) : "l"(smem));
    const u32 wb1_u32 = smem_base + 18560;
    const u32 w2s_u32 = smem_base + 34944;

    // map blockIdx.x -> (expert e, tile)
    int e = -1, tile = 0;
    {
        int t = blockIdx.x, acc = 0, prev = g_off[0];
#pragma unroll
        for (int ee = 0; ee < NEXP; ee++) {
            int nxt = g_off[ee + 1];
            int tiles_e = (nxt - prev + TM - 1) >> 5;
            if (e < 0 && t < acc + tiles_e) { e = ee; tile = t - acc; }
            acc += tiles_e;
            prev = nxt;
        }
        if (e < 0) return;
    }

    const int off0 = g_off[e];
    const int cnt  = g_off[e + 1] - off0;

    const int tid = threadIdx.x;
    const int tx  = tid & 15;        // 16 h/n-groups of 4
    const int ty  = tid >> 4;        // 8 token-groups of 4

    int rem = cnt - tile * TM;
    const int nt = rem > TM ? TM : rem;

    if (tid < TM) toks[tid] = g_perm[off0 + min(tile * TM + tid, cnt - 1)];
    __syncthreads();

    const float4* Xg   = (const float4*)x;
    const float*  W1e  = W1 + (size_t)e * DDIM * HDIM;
    const float*  W2e  = W2 + (size_t)e * HDIM * DDIM;

    const int tokA = tid & 31, kqA = tid >> 5;
    const int tokB = tokA,     kqB = kqA + 4;

    // ---- prologue: X chunk0 reg prefetch + cp.async W1 chunk0 / W2 slice0 ----
    float4 xv0 = Xg[(size_t)toks[tokA] * 64 + kqA];
    float4 xv1 = Xg[(size_t)toks[tokB] * 64 + kqB];
#pragma unroll
    for (int i = 0; i < 4; i++) {
        int f4 = tid + i * 128;                 // 0..511
        CPA16(wb1_u32 + f4 * 16, W1e + f4 * 4);               // W1 chunk0 -> buf0
        CPA16(w2s_u32 + f4 * 16, W2e + f4 * 4);               // W2 slice0
    }
    CPA_COMMIT();

    u64 acc2[2][4];
#pragma unroll
    for (int p = 0; p < 2; p++)
#pragma unroll
        for (int j = 0; j < 4; j++) acc2[p][j] = 0ull;

    // ================= GEMM1: 8 chunks of K=32 =================
    for (int c = 0; c < 8; c++) {
        const int b = c & 1;
        XS(b, kqA * 4 + 0, tokA) = xv0.x;
        XS(b, kqA * 4 + 1, tokA) = xv0.y;
        XS(b, kqA * 4 + 2, tokA) = xv0.z;
        XS(b, kqA * 4 + 3, tokA) = xv0.w;
        XS(b, kqB * 4 + 0, tokB) = xv1.x;
        XS(b, kqB * 4 + 1, tokB) = xv1.y;
        XS(b, kqB * 4 + 2, tokB) = xv1.z;
        XS(b, kqB * 4 + 3, tokB) = xv1.w;
        if (c < 7) {
            int k0 = (c + 1) * 32;
            xv0 = Xg[(size_t)toks[tokA] * 64 + (k0 >> 2) + kqA];
            xv1 = Xg[(size_t)toks[tokB] * 64 + (k0 >> 2) + kqB];
        }
        CPA_WAIT0();              // W1 chunk c (+W2 slice c) resident
        __syncthreads();
        if (c < 7) {
#pragma unroll
            for (int i = 0; i < 4; i++) {
                int f4 = tid + i * 128;
                CPA16(wb1_u32 + ((c + 1) & 1) * 8192 + f4 * 16,
                      W1e + (c + 1) * 2048 + f4 * 4);
                CPA16(w2s_u32 + (c + 1) * 8192 + f4 * 16,
                      W2e + (c + 1) * 2048 + f4 * 4);
            }
            CPA_COMMIT();
        }
#pragma unroll
        for (int k = 0; k < 32; k++) {
            ulonglong2 a = *(const ulonglong2*)&XS(b, k, ty * 4);
            float4 bb = *(const float4*)&WB1(b, k, tx * 4);
            u64 bd0, bd1, bd2, bd3;
            DUP2(bd0, bb.x); DUP2(bd1, bb.y); DUP2(bd2, bb.z); DUP2(bd3, bb.w);
            FMA2(acc2[0][0], a.x, bd0); FMA2(acc2[1][0], a.y, bd0);
            FMA2(acc2[0][1], a.x, bd1); FMA2(acc2[1][1], a.y, bd1);
            FMA2(acc2[0][2], a.x, bd2); FMA2(acc2[1][2], a.y, bd2);
            FMA2(acc2[0][3], a.x, bd3); FMA2(acc2[1][3], a.y, bd3);
        }
    }

    // bias + relu -> Hs[h][tok]
    {
        float4 bb = *(const float4*)&b1[e * HDIM + tx * 4];
        float bv[4] = {bb.x, bb.y, bb.z, bb.w};
#pragma unroll
        for (int p = 0; p < 2; p++) {
#pragma unroll
            for (int j = 0; j < 4; j++) {
                float lo, hi;
                UNPK(lo, hi, acc2[p][j]);
                lo += bv[j]; hi += bv[j];
                Hs[(tx * 4 + j) * 36 + ty * 4 + 2 * p]     = lo > 0.f ? lo : 0.f;
                Hs[(tx * 4 + j) * 36 + ty * 4 + 2 * p + 1] = hi > 0.f ? hi : 0.f;
            }
        }
    }
    __syncthreads();   // Hs complete; all W2 slices landed

    // ================= GEMM2: 4 chunks of 64 cols, zero staging/barriers ======
    for (int c = 0; c < 4; c++) {
#pragma unroll
        for (int p = 0; p < 2; p++)
#pragma unroll
            for (int j = 0; j < 4; j++) acc2[p][j] = 0ull;

#pragma unroll 16
        for (int k = 0; k < HDIM; k++) {
            ulonglong2 a = *(const ulonglong2*)&Hs[k * 36 + ty * 4];
            float4 bb = *(const float4*)&W2s[k * 256 + c * 64 + tx * 4];
            u64 bd0, bd1, bd2, bd3;
            DUP2(bd0, bb.x); DUP2(bd1, bb.y); DUP2(bd2, bb.z); DUP2(bd3, bb.w);
            FMA2(acc2[0][0], a.x, bd0); FMA2(acc2[1][0], a.y, bd0);
            FMA2(acc2[0][1], a.x, bd1); FMA2(acc2[1][1], a.y, bd1);
            FMA2(acc2[0][2], a.x, bd2); FMA2(acc2[1][2], a.y, bd2);
            FMA2(acc2[0][3], a.x, bd3); FMA2(acc2[1][3], a.y, bd3);
        }

        float4 cb = *(const float4*)&b2[e * DDIM + c * 64 + tx * 4];
        float cv[4] = {cb.x, cb.y, cb.z, cb.w};
        float r[4][4];
#pragma unroll
        for (int p = 0; p < 2; p++) {
#pragma unroll
            for (int j = 0; j < 4; j++) {
                float lo, hi;
                UNPK(lo, hi, acc2[p][j]);
                r[2 * p][j]     = fmaxf(lo + cv[j], 0.f);
                r[2 * p + 1][j] = fmaxf(hi + cv[j], 0.f);
            }
        }
#pragma unroll
        for (int i = 0; i < 4; i++) {
            int ti = ty * 4 + i;
            if (ti < nt) {
                size_t row = (size_t)toks[ti] * DDIM;
                float4 rv;
                rv.x = r[i][0]; rv.y = r[i][1]; rv.z = r[i][2]; rv.w = r[i][3];
                *(float4*)&out[row + c * 64 + tx * 4] = rv;
            }
        }
    }
#undef XS
#undef WB1
}

// ---------------- launch ----------------
#define FFN_SMEM 100480

extern "C" void kernel_launch(void* const* d_in, const int* in_sizes, int n_in,
                              void* d_out, int out_size) {
    const float* x   = (const float*)d_in[0];
    const float* rw  = (const float*)d_in[1];
    const float* rb  = (const float*)d_in[2];
    const float* W1  = (const float*)d_in[3];
    const float* b1  = (const float*)d_in[4];
    const float* W2  = (const float*)d_in[5];
    const float* b2  = (const float*)d_in[6];
    float* out = (float*)d_out;

    cudaFuncSetAttribute(k_ffn, cudaFuncAttributeMaxDynamicSharedMemorySize, FFN_SMEM);

    k_router<<<N_TOK / 32, 128>>>(x, rw, rb);
    k_scan<<<1, 32>>>();
    k_scatter<<<N_TOK / 256, 256>>>();
    k_ffn<<<FFN_CTAS, 128, FFN_SMEM>>>(x, W1, b1, W2, b2, out);
}

// round 16
// speedup vs baseline: 1.3744x; 1.0438x over previous
#include <cuda_runtime.h>
#include <cstdint>

#define N_TOK 8192
#define DDIM  256
#define HDIM  64
#define NEXP  32
#define TM    32        // tokens per ffn tile
#define FFN_CTAS 288    // >= max tiles: 8192/32=256 full + <=31 partial tails

typedef unsigned long long u64;
typedef unsigned int u32;

// packed-f32x2 helpers (sm_100+; ptxas never emits FFMA2 from C++)
#define DUP2(d, s)    asm("mov.b64 %0, {%1, %1};" : "=l"(d) : "f"(s))
#define FMA2(c, a, b) asm("fma.rn.f32x2 %0, %1, %2, %0;" : "+l"(c) : "l"(a), "l"(b))
#define UNPK(lo, hi, p) asm("mov.b64 {%0, %1}, %2;" : "=f"(lo), "=f"(hi) : "l"(p))

// cp.async 16B, L2-only (streaming weights)
#define CPA16(dst_u32, src_ptr) \
    asm volatile("cp.async.cg.shared.global [%0], [%1], 16;" :: "r"(dst_u32), "l"(src_ptr))
#define CPA_COMMIT()  asm volatile("cp.async.commit_group;")
#define CPA_WAIT0()   asm volatile("cp.async.wait_group 0;")

// ---------------- scratch (no allocations allowed; zero-init) ----------------
__device__ int g_cursor[NEXP];            // bucket cursors; final value = count.
                                          // FFN's last CTA resets each replay.
__device__ int g_perm[NEXP * N_TOK];      // fixed 8192-slot bucket per expert
__device__ int g_done;                    // FFN arrival counter (self-reset)

// ---------------- kernel 1: router GEMM + argmax + fused scatter ----------------
// 256 CTAs x 128 thr (~2 CTAs/SM). CTA tile: 32 tok x 32 exp, K=256 pipelined.
// Scalar thread tile 2 tok x 4 exp. Epilogue: first-max argmax -> block-
// aggregated scatter into per-expert buckets (1 cursor atomic/expert/CTA).
__global__ void __launch_bounds__(128) k_router(const float* __restrict__ x,
                                                const float* __restrict__ rw,
                                                const float* __restrict__ rb) {
    const int tid = threadIdx.x;
    const int tx  = tid & 7;       // expert group: experts tx*4..tx*4+3
    const int ty  = tid >> 3;      // token group: tokens 2ty, 2ty+1
    const int tok0 = blockIdx.x * 32;

    __shared__ float Xs[32][36];   // [k][tok]
    __shared__ float Ws[32][32];   // [k][exp]
    __shared__ int   tokE[32], hist[NEXP], sbase[NEXP], scur[NEXP];

    if (tid < NEXP) { hist[tid] = 0; scur[tid] = 0; }

    const float4* Xg = (const float4*)x;
    const float4* Wg = (const float4*)rw;

    // prefetch chunk 0 (X: 256 f4, W: 256 f4; 128 thr x 2 each)
    float4 xv[2], wv[2];
#pragma unroll
    for (int i = 0; i < 2; i++) {
        int lin = tid + i * 128;            // 0..255: row=lin&31, kq=lin>>5
        xv[i] = Xg[(size_t)(tok0 + (lin & 31)) * 64 + (lin >> 5)];
        wv[i] = Wg[(size_t)(lin & 31) * 64 + (lin >> 5)];
    }

    float acc[2][4];
#pragma unroll
    for (int i = 0; i < 2; i++)
#pragma unroll
        for (int j = 0; j < 4; j++) acc[i][j] = 0.f;

    for (int c = 0; c < 8; c++) {
        // STS prefetched chunk (transposed)
#pragma unroll
        for (int i = 0; i < 2; i++) {
            int lin = tid + i * 128;
            int row = lin & 31, kq = lin >> 5;
            Xs[kq * 4 + 0][row] = xv[i].x;
            Xs[kq * 4 + 1][row] = xv[i].y;
            Xs[kq * 4 + 2][row] = xv[i].z;
            Xs[kq * 4 + 3][row] = xv[i].w;
            Ws[kq * 4 + 0][row] = wv[i].x;   // row == expert index here
            Ws[kq * 4 + 1][row] = wv[i].y;
            Ws[kq * 4 + 2][row] = wv[i].z;
            Ws[kq * 4 + 3][row] = wv[i].w;
        }
        __syncthreads();
        // prefetch chunk c+1
        if (c < 7) {
            int kq0 = (c + 1) * 8;
#pragma unroll
            for (int i = 0; i < 2; i++) {
                int lin = tid + i * 128;
                xv[i] = Xg[(size_t)(tok0 + (lin & 31)) * 64 + kq0 + (lin >> 5)];
                wv[i] = Wg[(size_t)(lin & 31) * 64 + kq0 + (lin >> 5)];
            }
        }
        // compute chunk c: scalar, 2 LDS + 8 FFMA per k
#pragma unroll
        for (int k = 0; k < 32; k++) {
            float2 a = *(const float2*)&Xs[k][ty * 2];
            float4 b = *(const float4*)&Ws[k][tx * 4];
            acc[0][0] += a.x * b.x;  acc[1][0] += a.y * b.x;
            acc[0][1] += a.x * b.y;  acc[1][1] += a.y * b.y;
            acc[0][2] += a.x * b.z;  acc[1][2] += a.y * b.z;
            acc[0][3] += a.x * b.w;  acc[1][3] += a.y * b.w;
        }
        __syncthreads();
    }

    // epilogue: bias + first-max argmax (strict >, lower-idx ties)
    float4 rbv4 = *(const float4*)&rb[tx * 4];
    float rbv[4] = {rbv4.x, rbv4.y, rbv4.z, rbv4.w};
#pragma unroll
    for (int i = 0; i < 2; i++) {
        float v = acc[i][0] + rbv[0];
        int idx = tx * 4;
#pragma unroll
        for (int j = 1; j < 4; j++) {
            float val = acc[i][j] + rbv[j];
            if (val > v) { v = val; idx = tx * 4 + j; }
        }
        // reduce across the 8 expert-lanes (xor m<8 stays in token group)
#pragma unroll
        for (int m = 1; m < 8; m <<= 1) {
            float ov = __shfl_xor_sync(0xffffffffu, v, m);
            int   oi = __shfl_xor_sync(0xffffffffu, idx, m);
            if (ov > v || (ov == v && oi < idx)) { v = ov; idx = oi; }
        }
        if (tx == 0) {
            tokE[ty * 2 + i] = idx;
            atomicAdd(&hist[idx], 1);
        }
    }
    __syncthreads();
    // fused scatter: 1 cursor atomic per nonzero expert, then smem rank
    if (tid < NEXP && hist[tid]) sbase[tid] = atomicAdd(&g_cursor[tid], hist[tid]);
    __syncthreads();
    if (tid < 32) {
        int e = tokE[tid];
        int r = atomicAdd(&scur[e], 1);
        g_perm[e * N_TOK + sbase[e] + r] = tok0 + tid;
    }
}

// ---------------- kernel 2: grouped expert FFN (self-mapping, self-resetting) ----------------
// 288 CTAs x 128 thr (2 CTAs/SM @ 98KB dynamic smem). Maps (expert,tile) from
// g_cursor counts (fixed buckets, no scan). The 288th-arriving CTA resets
// g_cursor/g_done for the next graph replay (monotonic counter, no spinning).
// W1 chunks + W2 slices stream via cp.async; full 64KB W2 resident for GEMM2.
__global__ void __launch_bounds__(128) k_ffn(const float* __restrict__ x,
                                             const float* __restrict__ W1,
                                             const float* __restrict__ b1,
                                             const float* __restrict__ W2,
                                             const float* __restrict__ b2,
                                             float* __restrict__ out) {
    extern __shared__ __align__(16) char smem[];
    int*   toks = (int*)smem;
    float* Hs   = (float*)(smem + 128);
    float* XSb  = (float*)(smem + 9344);
    float* WB1b = (float*)(smem + 18560);
    float* W2s  = (float*)(smem + 34944);
#define XS(b,k,t)  XSb[(b)*1152 + (k)*36 + (t)]
#define WB1(b,k,h) WB1b[(b)*2048 + (k)*64 + (h)]

    u32 smem_base;
    asm("{ .reg .u64 t; cvta.to.shared.u64 t, %1; cvt.u32.u64 %0, t; }"
        : "=r"(smem_base) : "l"(smem));
    const u32 wb1_u32 = smem_base + 18560;
    const u32 w2s_u32 = smem_base + 34944;

    const int tid = threadIdx.x;

    // map blockIdx.x -> (expert e, tile) from bucket counts
    int e = -1, tile = 0, cnt = 0;
    {
        int t = blockIdx.x, acc = 0;
#pragma unroll
        for (int ee = 0; ee < NEXP; ee++) {
            int ce = g_cursor[ee];                 // final cursor == count
            int tiles_e = (ce + TM - 1) >> 5;
            if (e < 0 && t < acc + tiles_e) { e = ee; tile = t - acc; cnt = ce; }
            acc += tiles_e;
        }
    }
    // every thread's count-loads are consumed by the mapping arithmetic above;
    // the barrier makes the whole CTA's loads retired before tid0 arrives.
    __syncthreads();
    if (tid == 0) {
        int d = atomicAdd(&g_done, 1);
        if (d == FFN_CTAS - 1) {                   // last CTA: reset for next replay
#pragma unroll
            for (int i = 0; i < NEXP; i++) g_cursor[i] = 0;
            g_done = 0;
        }
    }
    if (e < 0) return;

    const int off0 = e * N_TOK;                    // fixed bucket base
    const int tx  = tid & 15;        // 16 h/n-groups of 4
    const int ty  = tid >> 4;        // 8 token-groups of 4

    int rem = cnt - tile * TM;
    const int nt = rem > TM ? TM : rem;

    if (tid < TM) toks[tid] = g_perm[off0 + min(tile * TM + tid, cnt - 1)];
    __syncthreads();

    const float4* Xg   = (const float4*)x;
    const float*  W1e  = W1 + (size_t)e * DDIM * HDIM;
    const float*  W2e  = W2 + (size_t)e * HDIM * DDIM;

    const int tokA = tid & 31, kqA = tid >> 5;
    const int tokB = tokA,     kqB = kqA + 4;

    // ---- prologue: X chunk0 reg prefetch + cp.async W1 chunk0 / W2 slice0 ----
    float4 xv0 = Xg[(size_t)toks[tokA] * 64 + kqA];
    float4 xv1 = Xg[(size_t)toks[tokB] * 64 + kqB];
#pragma unroll
    for (int i = 0; i < 4; i++) {
        int f4 = tid + i * 128;                 // 0..511
        CPA16(wb1_u32 + f4 * 16, W1e + f4 * 4);               // W1 chunk0 -> buf0
        CPA16(w2s_u32 + f4 * 16, W2e + f4 * 4);               // W2 slice0
    }
    CPA_COMMIT();

    u64 acc2[2][4];
#pragma unroll
    for (int p = 0; p < 2; p++)
#pragma unroll
        for (int j = 0; j < 4; j++) acc2[p][j] = 0ull;

    // ================= GEMM1: 8 chunks of K=32 =================
    for (int c = 0; c < 8; c++) {
        const int b = c & 1;
        XS(b, kqA * 4 + 0, tokA) = xv0.x;
        XS(b, kqA * 4 + 1, tokA) = xv0.y;
        XS(b, kqA * 4 + 2, tokA) = xv0.z;
        XS(b, kqA * 4 + 3, tokA) = xv0.w;
        XS(b, kqB * 4 + 0, tokB) = xv1.x;
        XS(b, kqB * 4 + 1, tokB) = xv1.y;
        XS(b, kqB * 4 + 2, tokB) = xv1.z;
        XS(b, kqB * 4 + 3, tokB) = xv1.w;
        if (c < 7) {
            int k0 = (c + 1) * 32;
            xv0 = Xg[(size_t)toks[tokA] * 64 + (k0 >> 2) + kqA];
            xv1 = Xg[(size_t)toks[tokB] * 64 + (k0 >> 2) + kqB];
        }
        CPA_WAIT0();              // W1 chunk c (+W2 slice c) resident
        __syncthreads();
        if (c < 7) {
#pragma unroll
            for (int i = 0; i < 4; i++) {
                int f4 = tid + i * 128;
                CPA16(wb1_u32 + ((c + 1) & 1) * 8192 + f4 * 16,
                      W1e + (c + 1) * 2048 + f4 * 4);
                CPA16(w2s_u32 + (c + 1) * 8192 + f4 * 16,
                      W2e + (c + 1) * 2048 + f4 * 4);
            }
            CPA_COMMIT();
        }
#pragma unroll
        for (int k = 0; k < 32; k++) {
            ulonglong2 a = *(const ulonglong2*)&XS(b, k, ty * 4);
            float4 bb = *(const float4*)&WB1(b, k, tx * 4);
            u64 bd0, bd1, bd2, bd3;
            DUP2(bd0, bb.x); DUP2(bd1, bb.y); DUP2(bd2, bb.z); DUP2(bd3, bb.w);
            FMA2(acc2[0][0], a.x, bd0); FMA2(acc2[1][0], a.y, bd0);
            FMA2(acc2[0][1], a.x, bd1); FMA2(acc2[1][1], a.y, bd1);
            FMA2(acc2[0][2], a.x, bd2); FMA2(acc2[1][2], a.y, bd2);
            FMA2(acc2[0][3], a.x, bd3); FMA2(acc2[1][3], a.y, bd3);
        }
    }

    // bias + relu -> Hs[h][tok]
    {
        float4 bb = *(const float4*)&b1[e * HDIM + tx * 4];
        float bv[4] = {bb.x, bb.y, bb.z, bb.w};
#pragma unroll
        for (int p = 0; p < 2; p++) {
#pragma unroll
            for (int j = 0; j < 4; j++) {
                float lo, hi;
                UNPK(lo, hi, acc2[p][j]);
                lo += bv[j]; hi += bv[j];
                Hs[(tx * 4 + j) * 36 + ty * 4 + 2 * p]     = lo > 0.f ? lo : 0.f;
                Hs[(tx * 4 + j) * 36 + ty * 4 + 2 * p + 1] = hi > 0.f ? hi : 0.f;
            }
        }
    }
    __syncthreads();   // Hs complete; all W2 slices landed

    // ================= GEMM2: 4 chunks of 64 cols, zero staging/barriers ======
    for (int c = 0; c < 4; c++) {
#pragma unroll
        for (int p = 0; p < 2; p++)
#pragma unroll
            for (int j = 0; j < 4; j++) acc2[p][j] = 0ull;

#pragma unroll 16
        for (int k = 0; k < HDIM; k++) {
            ulonglong2 a = *(const ulonglong2*)&Hs[k * 36 + ty * 4];
            float4 bb = *(const float4*)&W2s[k * 256 + c * 64 + tx * 4];
            u64 bd0, bd1, bd2, bd3;
            DUP2(bd0, bb.x); DUP2(bd1, bb.y); DUP2(bd2, bb.z); DUP2(bd3, bb.w);
            FMA2(acc2[0][0], a.x, bd0); FMA2(acc2[1][0], a.y, bd0);
            FMA2(acc2[0][1], a.x, bd1); FMA2(acc2[1][1], a.y, bd1);
            FMA2(acc2[0][2], a.x, bd2); FMA2(acc2[1][2], a.y, bd2);
            FMA2(acc2[0][3], a.x, bd3); FMA2(acc2[1][3], a.y, bd3);
        }

        float4 cb = *(const float4*)&b2[e * DDIM + c * 64 + tx * 4];
        float cv[4] = {cb.x, cb.y, cb.z, cb.w};
        float r[4][4];
#pragma unroll
        for (int p = 0; p < 2; p++) {
#pragma unroll
            for (int j = 0; j < 4; j++) {
                float lo, hi;
                UNPK(lo, hi, acc2[p][j]);
                r[2 * p][j]     = fmaxf(lo + cv[j], 0.f);
                r[2 * p + 1][j] = fmaxf(hi + cv[j], 0.f);
            }
        }
#pragma unroll
        for (int i = 0; i < 4; i++) {
            int ti = ty * 4 + i;
            if (ti < nt) {
                size_t row = (size_t)toks[ti] * DDIM;
                float4 rv;
                rv.x = r[i][0]; rv.y = r[i][1]; rv.z = r[i][2]; rv.w = r[i][3];
                *(float4*)&out[row + c * 64 + tx * 4] = rv;
            }
        }
    }
#undef XS
#undef WB1
}

// ---------------- launch ----------------
#define FFN_SMEM 100480

extern "C" void kernel_launch(void* const* d_in, const int* in_sizes, int n_in,
                              void* d_out, int out_size) {
    const float* x   = (const float*)d_in[0];
    const float* rw  = (const float*)d_in[1];
    const float* rb  = (const float*)d_in[2];
    const float* W1  = (const float*)d_in[3];
    const float* b1  = (const float*)d_in[4];
    const float* W2  = (const float*)d_in[5];
    const float* b2  = (const float*)d_in[6];
    float* out = (float*)d_out;

    cudaFuncSetAttribute(k_ffn, cudaFuncAttributeMaxDynamicSharedMemorySize, FFN_SMEM);

    k_router<<<N_TOK / 32, 128>>>(x, rw, rb);
    k_ffn<<<FFN_CTAS, 128, FFN_SMEM>>>(x, W1, b1, W2, b2, out);
}

// round 17
// speedup vs baseline: 1.3931x; 1.0136x over previous
#include <cuda_runtime.h>
#include <cstdint>

#define N_TOK 8192
#define DDIM  256
#define HDIM  64
#define NEXP  32
#define TM    32        // tokens per ffn tile
#define FFN_CTAS 288    // >= max tiles: 8192/32=256 full + <=31 partial tails

typedef unsigned long long u64;
typedef unsigned int u32;

// cp.async 16B, L2-only (streaming weights)
#define CPA16(dst_u32, src_ptr) \
    asm volatile("cp.async.cg.shared.global [%0], [%1], 16;" :: "r"(dst_u32), "l"(src_ptr))
#define CPA_COMMIT()  asm volatile("cp.async.commit_group;")
#define CPA_WAIT0()   asm volatile("cp.async.wait_group 0;")

// 3xTF32 split: x ~= hi + lo with hi,lo tf32-representable (error ~2^-22)
__device__ __forceinline__ void tf32split(float x, u32& hi, u32& lo) {
    asm("cvt.rna.tf32.f32 %0, %1;" : "=r"(hi) : "f"(x));
    float r = x - __uint_as_float(hi);
    asm("cvt.rna.tf32.f32 %0, %1;" : "=r"(lo) : "f"(r));
}

// m16n8k8 tf32 MMA, fp32 accumulate (canonical sm_80+ fragment layout)
__device__ __forceinline__ void mma_tf32(float* c, const u32* a, const u32* b) {
    asm volatile("mma.sync.aligned.m16n8k8.row.col.f32.tf32.tf32.f32 "
        "{%0,%1,%2,%3}, {%4,%5,%6,%7}, {%8,%9}, {%0,%1,%2,%3};"
        : "+f"(c[0]), "+f"(c[1]), "+f"(c[2]), "+f"(c[3])
        : "r"(a[0]), "r"(a[1]), "r"(a[2]), "r"(a[3]), "r"(b[0]), "r"(b[1]));
}

// ---------------- scratch (no allocations allowed; zero-init) ----------------
__device__ int g_cursor[NEXP];            // bucket cursors; final value = count
__device__ int g_perm[NEXP * N_TOK];      // fixed 8192-slot bucket per expert
__device__ int g_done;                    // FFN arrival counter (self-reset)

// ---------------- kernel 1: router GEMM + argmax + fused scatter (R16) ----------------
__global__ void __launch_bounds__(128) k_router(const float* __restrict__ x,
                                                const float* __restrict__ rw,
                                                const float* __restrict__ rb) {
    const int tid = threadIdx.x;
    const int tx  = tid & 7;
    const int ty  = tid >> 3;
    const int tok0 = blockIdx.x * 32;

    __shared__ float Xs[32][36];
    __shared__ float Ws[32][32];
    __shared__ int   tokE[32], hist[NEXP], sbase[NEXP], scur[NEXP];

    if (tid < NEXP) { hist[tid] = 0; scur[tid] = 0; }

    const float4* Xg = (const float4*)x;
    const float4* Wg = (const float4*)rw;

    float4 xv[2], wv[2];
#pragma unroll
    for (int i = 0; i < 2; i++) {
        int lin = tid + i * 128;
        xv[i] = Xg[(size_t)(tok0 + (lin & 31)) * 64 + (lin >> 5)];
        wv[i] = Wg[(size_t)(lin & 31) * 64 + (lin >> 5)];
    }

    float acc[2][4];
#pragma unroll
    for (int i = 0; i < 2; i++)
#pragma unroll
        for (int j = 0; j < 4; j++) acc[i][j] = 0.f;

    for (int c = 0; c < 8; c++) {
#pragma unroll
        for (int i = 0; i < 2; i++) {
            int lin = tid + i * 128;
            int row = lin & 31, kq = lin >> 5;
            Xs[kq * 4 + 0][row] = xv[i].x;
            Xs[kq * 4 + 1][row] = xv[i].y;
            Xs[kq * 4 + 2][row] = xv[i].z;
            Xs[kq * 4 + 3][row] = xv[i].w;
            Ws[kq * 4 + 0][row] = wv[i].x;
            Ws[kq * 4 + 1][row] = wv[i].y;
            Ws[kq * 4 + 2][row] = wv[i].z;
            Ws[kq * 4 + 3][row] = wv[i].w;
        }
        __syncthreads();
        if (c < 7) {
            int kq0 = (c + 1) * 8;
#pragma unroll
            for (int i = 0; i < 2; i++) {
                int lin = tid + i * 128;
                xv[i] = Xg[(size_t)(tok0 + (lin & 31)) * 64 + kq0 + (lin >> 5)];
                wv[i] = Wg[(size_t)(lin & 31) * 64 + kq0 + (lin >> 5)];
            }
        }
#pragma unroll
        for (int k = 0; k < 32; k++) {
            float2 a = *(const float2*)&Xs[k][ty * 2];
            float4 b = *(const float4*)&Ws[k][tx * 4];
            acc[0][0] += a.x * b.x;  acc[1][0] += a.y * b.x;
            acc[0][1] += a.x * b.y;  acc[1][1] += a.y * b.y;
            acc[0][2] += a.x * b.z;  acc[1][2] += a.y * b.z;
            acc[0][3] += a.x * b.w;  acc[1][3] += a.y * b.w;
        }
        __syncthreads();
    }

    float4 rbv4 = *(const float4*)&rb[tx * 4];
    float rbv[4] = {rbv4.x, rbv4.y, rbv4.z, rbv4.w};
#pragma unroll
    for (int i = 0; i < 2; i++) {
        float v = acc[i][0] + rbv[0];
        int idx = tx * 4;
#pragma unroll
        for (int j = 1; j < 4; j++) {
            float val = acc[i][j] + rbv[j];
            if (val > v) { v = val; idx = tx * 4 + j; }   // strict > = first-max
        }
#pragma unroll
        for (int m = 1; m < 8; m <<= 1) {
            float ov = __shfl_xor_sync(0xffffffffu, v, m);
            int   oi = __shfl_xor_sync(0xffffffffu, idx, m);
            if (ov > v || (ov == v && oi < idx)) { v = ov; idx = oi; }
        }
        if (tx == 0) {
            tokE[ty * 2 + i] = idx;
            atomicAdd(&hist[idx], 1);
        }
    }
    __syncthreads();
    if (tid < NEXP && hist[tid]) sbase[tid] = atomicAdd(&g_cursor[tid], hist[tid]);
    __syncthreads();
    if (tid < 32) {
        int e = tokE[tid];
        int r = atomicAdd(&scur[e], 1);
        g_perm[e * N_TOK + sbase[e] + r] = tok0 + tid;
    }
}

// ---------------- kernel 2: grouped expert FFN — tensor-core 3xTF32 ----------------
// 288 CTAs x 128 thr (2 CTAs/SM @ ~100KB dynamic smem). Same staging pipeline
// as R16 (cp.async W1 double-buffer, full W2 resident); inner products are
// mma.sync.m16n8k8 tf32 with 3xTF32 split (fp32-grade accuracy).
// smem layout (bytes):
//  [0,128) toks | [128,8832) Hs[32][68] | [8832,18048) XS 2x32x36
//  [18048,35456) WB1 2x32x68 | [35456,102016) W2s 64x260
__global__ void __launch_bounds__(128) k_ffn(const float* __restrict__ x,
                                             const float* __restrict__ W1,
                                             const float* __restrict__ b1,
                                             const float* __restrict__ W2,
                                             const float* __restrict__ b2,
                                             float* __restrict__ out) {
    extern __shared__ __align__(16) char smem[];
    int*   toks = (int*)smem;
    float* HsF  = (float*)(smem + 128);
    float* XSb  = (float*)(smem + 8832);
    float* WB1f = (float*)(smem + 18048);
    float* W2s  = (float*)(smem + 35456);
#define XS(b,k,t)  XSb[(b)*1152 + (k)*36 + (t)]
#define WB1(b,k,h) WB1f[(b)*2176 + (k)*68 + (h)]

    u32 smem_base;
    asm("{ .reg .u64 t; cvta.to.shared.u64 t, %1; cvt.u32.u64 %0, t; }"
        : "=r"(smem_base) : "l"(smem));
    const u32 wb1_u32 = smem_base + 18048;
    const u32 w2s_u32 = smem_base + 35456;

    const int tid = threadIdx.x;

    // map blockIdx.x -> (expert e, tile) from bucket counts
    int e = -1, tile = 0, cnt = 0;
    {
        int t = blockIdx.x, acc = 0;
#pragma unroll
        for (int ee = 0; ee < NEXP; ee++) {
            int ce = g_cursor[ee];
            int tiles_e = (ce + TM - 1) >> 5;
            if (e < 0 && t < acc + tiles_e) { e = ee; tile = t - acc; cnt = ce; }
            acc += tiles_e;
        }
    }
    __syncthreads();
    if (tid == 0) {
        int d = atomicAdd(&g_done, 1);
        if (d == FFN_CTAS - 1) {
#pragma unroll
            for (int i = 0; i < NEXP; i++) g_cursor[i] = 0;
            g_done = 0;
        }
    }
    if (e < 0) return;

    const int off0 = e * N_TOK;
    const int warp = tid >> 5;
    const int lane = tid & 31;
    const int gid  = lane >> 2;      // 0..7
    const int tg   = lane & 3;       // 0..3
    const int wn   = warp * 16;      // GEMM1 n-base
    const int wn2  = warp * 64;      // GEMM2 n-base

    int rem = cnt - tile * TM;
    const int nvalid = rem > TM ? TM : rem;

    if (tid < TM) toks[tid] = g_perm[off0 + min(tile * TM + tid, cnt - 1)];
    __syncthreads();

    const float4* Xg  = (const float4*)x;
    const float*  W1e = W1 + (size_t)e * DDIM * HDIM;
    const float*  W2e = W2 + (size_t)e * HDIM * DDIM;

    const int tokA = tid & 31, kqA = tid >> 5;
    const int tokB = tokA,     kqB = kqA + 4;

    // ---- prologue: X chunk0 reg prefetch + cp.async W1 chunk0 / W2 slice0 ----
    float4 xv0 = Xg[(size_t)toks[tokA] * 64 + kqA];
    float4 xv1 = Xg[(size_t)toks[tokB] * 64 + kqB];
#pragma unroll
    for (int i = 0; i < 4; i++) {
        int f4 = tid + i * 128;                       // 0..511
        int k  = f4 >> 4, h4 = f4 & 15;
        CPA16(wb1_u32 + k * 272 + h4 * 16, W1e + f4 * 4);      // W1 chunk0 (stride 68)
        int kr = f4 >> 6, n4 = f4 & 63;
        CPA16(w2s_u32 + kr * 1040 + n4 * 16, W2e + f4 * 4);    // W2 slice0 (stride 260)
    }
    CPA_COMMIT();

    float acc1[2][2][4];
#pragma unroll
    for (int mt = 0; mt < 2; mt++)
#pragma unroll
        for (int n = 0; n < 2; n++)
#pragma unroll
            for (int j = 0; j < 4; j++) acc1[mt][n][j] = 0.f;

    // ================= GEMM1: 8 chunks of K=32, tensor mma =================
    for (int c = 0; c < 8; c++) {
        const int b = c & 1;
        XS(b, kqA * 4 + 0, tokA) = xv0.x;
        XS(b, kqA * 4 + 1, tokA) = xv0.y;
        XS(b, kqA * 4 + 2, tokA) = xv0.z;
        XS(b, kqA * 4 + 3, tokA) = xv0.w;
        XS(b, kqB * 4 + 0, tokB) = xv1.x;
        XS(b, kqB * 4 + 1, tokB) = xv1.y;
        XS(b, kqB * 4 + 2, tokB) = xv1.z;
        XS(b, kqB * 4 + 3, tokB) = xv1.w;
        if (c < 7) {
            int k0 = (c + 1) * 32;
            xv0 = Xg[(size_t)toks[tokA] * 64 + (k0 >> 2) + kqA];
            xv1 = Xg[(size_t)toks[tokB] * 64 + (k0 >> 2) + kqB];
        }
        CPA_WAIT0();              // W1 chunk c (+W2 slice c) resident
        __syncthreads();
        if (c < 7) {
#pragma unroll
            for (int i = 0; i < 4; i++) {
                int f4 = tid + i * 128;
                int k  = f4 >> 4, h4 = f4 & 15;
                CPA16(wb1_u32 + ((c + 1) & 1) * 8704 + k * 272 + h4 * 16,
                      W1e + (c + 1) * 2048 + f4 * 4);
                int kr = f4 >> 6, n4 = f4 & 63;
                CPA16(w2s_u32 + (c + 1) * 8320 + kr * 1040 + n4 * 16,
                      W2e + (c + 1) * 2048 + f4 * 4);
            }
            CPA_COMMIT();
        }
        // compute chunk c: 4 k-steps of m16n8k8
#pragma unroll
        for (int kk = 0; kk < 4; kk++) {
            const int k0 = kk * 8;
            u32 ahi[2][4], alo[2][4];
#pragma unroll
            for (int mt = 0; mt < 2; mt++) {
                float a0 = XS(b, k0 + tg,     mt * 16 + gid);
                float a1 = XS(b, k0 + tg,     mt * 16 + gid + 8);
                float a2 = XS(b, k0 + tg + 4, mt * 16 + gid);
                float a3 = XS(b, k0 + tg + 4, mt * 16 + gid + 8);
                tf32split(a0, ahi[mt][0], alo[mt][0]);
                tf32split(a1, ahi[mt][1], alo[mt][1]);
                tf32split(a2, ahi[mt][2], alo[mt][2]);
                tf32split(a3, ahi[mt][3], alo[mt][3]);
            }
#pragma unroll
            for (int n = 0; n < 2; n++) {
                float b0 = WB1(b, k0 + tg,     wn + n * 8 + gid);
                float b1v = WB1(b, k0 + tg + 4, wn + n * 8 + gid);
                u32 bhi[2], blo[2];
                tf32split(b0, bhi[0], blo[0]);
                tf32split(b1v, bhi[1], blo[1]);
#pragma unroll
                for (int mt = 0; mt < 2; mt++) {
                    mma_tf32(acc1[mt][n], ahi[mt], bhi);
                    mma_tf32(acc1[mt][n], ahi[mt], blo);
                    mma_tf32(acc1[mt][n], alo[mt], bhi);
                }
            }
        }
    }

    // GEMM1 epilogue: bias + relu -> Hs[tok][h] (row stride 68)
#pragma unroll
    for (int mt = 0; mt < 2; mt++)
#pragma unroll
        for (int n = 0; n < 2; n++) {
            int h0 = wn + n * 8 + 2 * tg;
            float bias0 = b1[e * HDIM + h0];
            float bias1 = b1[e * HDIM + h0 + 1];
            float* cc = acc1[mt][n];
            float2 v0, v1;
            v0.x = fmaxf(cc[0] + bias0, 0.f);
            v0.y = fmaxf(cc[1] + bias1, 0.f);
            v1.x = fmaxf(cc[2] + bias0, 0.f);
            v1.y = fmaxf(cc[3] + bias1, 0.f);
            *(float2*)&HsF[(mt * 16 + gid) * 68 + h0]     = v0;
            *(float2*)&HsF[(mt * 16 + gid + 8) * 68 + h0] = v1;
        }
    __syncthreads();   // Hs complete; all W2 slices landed (waited at c=7)

    // ================= GEMM2: 32x256, K=64, tensor mma, barrier-free =========
    float acc2[2][8][4];
#pragma unroll
    for (int mt = 0; mt < 2; mt++)
#pragma unroll
        for (int n = 0; n < 8; n++)
#pragma unroll
            for (int j = 0; j < 4; j++) acc2[mt][n][j] = 0.f;

#pragma unroll
    for (int kk = 0; kk < 8; kk++) {
        const int k0 = kk * 8;
        u32 ahi[2][4], alo[2][4];
#pragma unroll
        for (int mt = 0; mt < 2; mt++) {
            float a0 = HsF[(mt * 16 + gid) * 68 + k0 + tg];
            float a1 = HsF[(mt * 16 + gid + 8) * 68 + k0 + tg];
            float a2 = HsF[(mt * 16 + gid) * 68 + k0 + tg + 4];
            float a3 = HsF[(mt * 16 + gid + 8) * 68 + k0 + tg + 4];
            tf32split(a0, ahi[mt][0], alo[mt][0]);
            tf32split(a1, ahi[mt][1], alo[mt][1]);
            tf32split(a2, ahi[mt][2], alo[mt][2]);
            tf32split(a3, ahi[mt][3], alo[mt][3]);
        }
#pragma unroll
        for (int n = 0; n < 8; n++) {
            float b0  = W2s[(k0 + tg) * 260 + wn2 + n * 8 + gid];
            float b1v = W2s[(k0 + tg + 4) * 260 + wn2 + n * 8 + gid];
            u32 bhi[2], blo[2];
            tf32split(b0, bhi[0], blo[0]);
            tf32split(b1v, bhi[1], blo[1]);
#pragma unroll
            for (int mt = 0; mt < 2; mt++) {
                mma_tf32(acc2[mt][n], ahi[mt], bhi);
                mma_tf32(acc2[mt][n], ahi[mt], blo);
                mma_tf32(acc2[mt][n], alo[mt], bhi);
            }
        }
    }

    // GEMM2 epilogue: bias + relu + store
#pragma unroll
    for (int mt = 0; mt < 2; mt++)
#pragma unroll
        for (int n = 0; n < 8; n++) {
            int d0 = wn2 + n * 8 + 2 * tg;
            float bias0 = b2[e * DDIM + d0];
            float bias1 = b2[e * DDIM + d0 + 1];
            float* cc = acc2[mt][n];
            int r0 = mt * 16 + gid;
            int r1 = r0 + 8;
            if (r0 < nvalid) {
                float2 v;
                v.x = fmaxf(cc[0] + bias0, 0.f);
                v.y = fmaxf(cc[1] + bias1, 0.f);
                *(float2*)&out[(size_t)toks[r0] * DDIM + d0] = v;
            }
            if (r1 < nvalid) {
                float2 v;
                v.x = fmaxf(cc[2] + bias0, 0.f);
                v.y = fmaxf(cc[3] + bias1, 0.f);
                *(float2*)&out[(size_t)toks[r1] * DDIM + d0] = v;
            }
        }
#undef XS
#undef WB1
}

// ---------------- launch ----------------
#define FFN_SMEM 102016

extern "C" void kernel_launch(void* const* d_in, const int* in_sizes, int n_in,
                              void* d_out, int out_size) {
    const float* x   = (const float*)d_in[0];
    const float* rw  = (const float*)d_in[1];
    const float* rb  = (const float*)d_in[2];
    const float* W1  = (const float*)d_in[3];
    const float* b1  = (const float*)d_in[4];
    const float* W2  = (const float*)d_in[5];
    const float* b2  = (const float*)d_in[6];
    float* out = (float*)d_out;

    cudaFuncSetAttribute(k_ffn, cudaFuncAttributeMaxDynamicSharedMemorySize, FFN_SMEM);

    k_router<<<N_TOK / 32, 128>>>(x, rw, rb);
    k_ffn<<<FFN_CTAS, 128, FFN_SMEM>>>(x, W1, b1, W2, b2, out);
}